// round 6
// baseline (speedup 1.0000x reference)
#include <cuda_runtime.h>
#include <cuda_fp16.h>
#include <cstdint>
#include <math.h>

// ---------------------------------------------------------------------------
// AttentionFusion on GB300 (sm_103): fp16 mma.sync GEMMs, 128x256 CTA tile,
// 64x64 warp tile, fused elementwise.  B=16384, E=512, H=8, HD=64, NC=6.
// ---------------------------------------------------------------------------

#define BATCH 16384

// fp16 scratch
__device__ __half g_rgb_h [BATCH * 768];
__device__ __half g_pose_h[BATCH * 640];
__device__ __half g_flow_h[BATCH * 1024];
__device__ __half g_proj_h[BATCH * 1536];   // (B,3,512), post-LN in-place
__device__ __half g_qkv_h [BATCH * 4608];   // (B*3, 1536) rows
__device__ __half g_ctx_h [BATCH * 1536];
__device__ __half g_att_h [BATCH * 1536];
__device__ __half g_gh_h  [BATCH * 512];
__device__ __half g_fused_h[BATCH * 512];
// fp16 weights
__device__ __half g_rgbw_h [512 * 768];
__device__ __half g_posew_h[512 * 640];
__device__ __half g_floww_h[512 * 1024];
__device__ __half g_inw_h  [1536 * 512];
__device__ __half g_outw_h [512 * 512];
__device__ __half g_gw1_h  [512 * 1536];
__device__ __half g_cw1_h  [256 * 512];
// fp32 scratch
__device__ float g_chid[BATCH * 256];

__device__ __forceinline__ uint32_t smem_u32(const void* p) {
    uint32_t a;
    asm("{ .reg .u64 t; cvta.to.shared.u64 t, %1; cvt.u32.u64 %0, t; }"
        : "=r"(a) : "l"(p));
    return a;
}

// ---------------------------------------------------------------------------
// single fused fp32->fp16 convert over all inputs+weights (compile-time table)
// ---------------------------------------------------------------------------
struct CvtArgs {
    const float* src[10];
    __half* dst[10];
};
// element counts (all % 8 == 0)
__device__ __constant__ const long CVT_END[10] = {
    12582912,              // rgb     16384*768
    23068672,              // pose    +16384*640
    39845888,              // flow    +16384*1024
    40239104,              // rgbw    +512*768
    40566784,              // posew   +512*640
    41091072,              // floww   +512*1024
    41877504,              // inw     +1536*512
    42139648,              // outw    +512*512
    42926080,              // gw1     +512*1536
    43057152               // cw1     +256*512
};
constexpr long CVT_TOTAL8 = 43057152 / 8;   // 5382144 vec8 units

__global__ void __launch_bounds__(256) f2h_all(CvtArgs args)
{
    long v = (long)blockIdx.x * 256 + threadIdx.x;
    if (v >= CVT_TOTAL8) return;
    long i = v * 8;
    int s = 0;
#pragma unroll
    for (int k = 0; k < 10; k++)
        if (i >= CVT_END[k]) s = k + 1;
    long base = (s == 0) ? 0 : CVT_END[s - 1];
    long off = i - base;
    const float* in = args.src[s] + off;
    __half* out = args.dst[s] + off;
    float4 v0 = *reinterpret_cast<const float4*>(in);
    float4 v1 = *reinterpret_cast<const float4*>(in + 4);
    union { uint4 u; __half2 h[4]; } pk;
    pk.h[0] = __floats2half2_rn(v0.x, v0.y);
    pk.h[1] = __floats2half2_rn(v0.z, v0.w);
    pk.h[2] = __floats2half2_rn(v1.x, v1.y);
    pk.h[3] = __floats2half2_rn(v1.z, v1.w);
    *reinterpret_cast<uint4*>(out) = pk.u;
}

// ---------------------------------------------------------------------------
// fp16 tensor-core GEMM: C[M,N] = A[M,K] * W[N,K]^T + bias (torch Linear)
// BM=128, BN=256, BK=64 halves; 256 threads = 8 warps (2m x 4n), warp 64x64.
// 3-stage cp.async pipeline (48KB/stage), SW128 swizzle, ldmatrix.x4,
// mma.m16n8k16.f32.f16.  Requires M%128==0, N%256==0, K%64==0, K>=192.
// ---------------------------------------------------------------------------
constexpr int W_STAGEB = 49152;               // A 16K + B 32K
constexpr int W_SMEM   = 3 * W_STAGEB;        // 147456

__device__ __forceinline__ void storePair(float v0, float v1, __half* p) {
    *reinterpret_cast<__half2*>(p) = __floats2half2_rn(v0, v1);
}
__device__ __forceinline__ void storePair(float v0, float v1, float* p) {
    *reinterpret_cast<float2*>(p) = make_float2(v0, v1);
}

template<int RELU, typename OT>
__global__ void __launch_bounds__(256, 1) gemm_w(
    const __half* __restrict__ A, const __half* __restrict__ W,
    const float* __restrict__ bias, OT* __restrict__ C,
    int K, int ldc)
{
    extern __shared__ __align__(16) char smem[];
    const uint32_t sb = smem_u32(smem);
    const int tid = threadIdx.x;
    const int wid = tid >> 5, lane = tid & 31;
    const int q  = lane >> 2, kr = lane & 3;
    const int wm = wid & 1,  wn = wid >> 1;          // 2m x 4n
    const int bm = blockIdx.y * 128, bn = blockIdx.x * 256;

    // cp.async mapping:
    //   A (16KB): thread covers row tid>>1, segs (tid&1)*4 .. +3
    //   B (32KB): thread covers row tid, all 8 segs
    const int lrowA = tid >> 1;
    const __half* Arow = A + (size_t)(bm + lrowA) * K + (tid & 1) * 32;
    const __half* Wrow = W + (size_t)(bn + tid) * K;
    uint32_t dstA[4], dstB[8];
    {
        const uint32_t rowbA = (uint32_t)lrowA * 128;
        const uint32_t mA = (lrowA & 7) << 4;
#pragma unroll
        for (int i = 0; i < 4; i++) {
            const uint32_t seg = (tid & 1) * 4 + i;
            dstA[i] = sb + rowbA + ((seg * 16) ^ mA);
        }
        const uint32_t rowbB = 16384u + (uint32_t)tid * 128;
        const uint32_t mB = (tid & 7) << 4;
#pragma unroll
        for (int i = 0; i < 8; i++)
            dstB[i] = sb + rowbB + (((uint32_t)i * 16) ^ mB);
    }

#define LOAD_CHUNK(kc_) do {                                                  \
        const uint32_t st_ = ((kc_) % 3) * W_STAGEB;                          \
        const __half* ap_ = Arow + (size_t)(kc_) * 64;                        \
        const __half* wp_ = Wrow + (size_t)(kc_) * 64;                        \
        _Pragma("unroll")                                                     \
        for (int i = 0; i < 4; i++)                                           \
            asm volatile("cp.async.cg.shared.global [%0], [%1], 16;"          \
                :: "r"(dstA[i] + st_), "l"(ap_ + i * 8) : "memory");          \
        _Pragma("unroll")                                                     \
        for (int i = 0; i < 8; i++)                                           \
            asm volatile("cp.async.cg.shared.global [%0], [%1], 16;"          \
                :: "r"(dstB[i] + st_), "l"(wp_ + i * 8) : "memory");          \
        asm volatile("cp.async.commit_group;" ::: "memory");                  \
    } while (0)

    const int KC = K >> 6;
    LOAD_CHUNK(0); LOAD_CHUNK(1); LOAD_CHUNK(2);

    // ldmatrix address components
    uint32_t rowbA[4], mAr[4], rowbB[4], mBr[4];
    const uint32_t colA0 = (lane >> 4) * 16;
    const uint32_t colB0 = ((lane >> 3) & 1) * 16;
#pragma unroll
    for (int t = 0; t < 4; t++) {
        const uint32_t r = wm * 64 + t * 16 + (lane & 15);
        rowbA[t] = r * 128; mAr[t] = (r & 7) << 4;
    }
#pragma unroll
    for (int jj = 0; jj < 4; jj++) {
        const uint32_t r = wn * 64 + jj * 16 + (lane & 7) + ((lane >> 4) & 1) * 8;
        rowbB[jj] = 16384u + r * 128; mBr[jj] = (r & 7) << 4;
    }

    float c[4][8][4];
#pragma unroll
    for (int t = 0; t < 4; t++)
#pragma unroll
        for (int j = 0; j < 8; j++)
#pragma unroll
            for (int r = 0; r < 4; r++) c[t][j][r] = 0.f;

    for (int kc = 0; kc < KC; kc++) {
        asm volatile("cp.async.wait_group 2;" ::: "memory");
        __syncthreads();
        const uint32_t St = sb + (kc % 3) * W_STAGEB;
#pragma unroll
        for (int ks = 0; ks < 4; ks++) {
            uint32_t a[4][4], b[4][4];
#pragma unroll
            for (int t = 0; t < 4; t++) {
                const uint32_t ad = St + rowbA[t] + ((colA0 + ks * 32) ^ mAr[t]);
                asm volatile(
                    "ldmatrix.sync.aligned.m8n8.x4.shared.b16 {%0,%1,%2,%3}, [%4];"
                    : "=r"(a[t][0]), "=r"(a[t][1]), "=r"(a[t][2]), "=r"(a[t][3])
                    : "r"(ad));
            }
#pragma unroll
            for (int jj = 0; jj < 4; jj++) {
                const uint32_t bd = St + rowbB[jj] + ((colB0 + ks * 32) ^ mBr[jj]);
                asm volatile(
                    "ldmatrix.sync.aligned.m8n8.x4.shared.b16 {%0,%1,%2,%3}, [%4];"
                    : "=r"(b[jj][0]), "=r"(b[jj][1]), "=r"(b[jj][2]), "=r"(b[jj][3])
                    : "r"(bd));
            }
#pragma unroll
            for (int t = 0; t < 4; t++)
#pragma unroll
                for (int j = 0; j < 8; j++) {
                    const int jj = j >> 1, lo = (j & 1) * 2;
                    asm volatile(
                        "mma.sync.aligned.m16n8k16.row.col.f32.f16.f16.f32 "
                        "{%0,%1,%2,%3}, {%4,%5,%6,%7}, {%8,%9}, {%0,%1,%2,%3};"
                        : "+f"(c[t][j][0]), "+f"(c[t][j][1]),
                          "+f"(c[t][j][2]), "+f"(c[t][j][3])
                        : "r"(a[t][0]), "r"(a[t][1]), "r"(a[t][2]), "r"(a[t][3]),
                          "r"(b[jj][lo]), "r"(b[jj][lo + 1]));
                }
        }
        __syncthreads();
        const int kn = kc + 3;
        if (kn < KC) { LOAD_CHUNK(kn); }
        else asm volatile("cp.async.commit_group;" ::: "memory");
    }
#undef LOAD_CHUNK

    // epilogue: bias (+ReLU)
#pragma unroll
    for (int t = 0; t < 4; t++) {
        const int r0 = bm + wm * 64 + t * 16 + q;
#pragma unroll
        for (int j = 0; j < 8; j++) {
            const int col = bn + wn * 64 + j * 8 + (kr << 1);
            const float b0 = bias[col], b1 = bias[col + 1];
            float v00 = c[t][j][0] + b0, v01 = c[t][j][1] + b1;
            float v10 = c[t][j][2] + b0, v11 = c[t][j][3] + b1;
            if (RELU) {
                v00 = fmaxf(v00, 0.f); v01 = fmaxf(v01, 0.f);
                v10 = fmaxf(v10, 0.f); v11 = fmaxf(v11, 0.f);
            }
            storePair(v00, v01, C + (size_t)r0 * ldc + col);
            storePair(v10, v11, C + (size_t)(r0 + 8) * ldc + col);
        }
    }
}

// ---------------------------------------------------------------------------
// elementwise / small kernels
// ---------------------------------------------------------------------------
__device__ __forceinline__ float warpSum(float v) {
#pragma unroll
    for (int o = 16; o > 0; o >>= 1) v += __shfl_xor_sync(0xffffffffu, v, o);
    return v;
}

__device__ __forceinline__ float blockSum128(float v, float* sred) {
    int lane = threadIdx.x & 31, w = threadIdx.x >> 5;
    v = warpSum(v);
    __syncthreads();
    if (lane == 0) sred[w] = v;
    __syncthreads();
    return sred[0] + sred[1] + sred[2] + sred[3];
}

// in-place LN+ReLU on fp16 rows of 512; modality = row % 3
__global__ void __launch_bounds__(128) ln_relu3_h(
    __half* __restrict__ x,
    const float* __restrict__ g0, const float* __restrict__ be0,
    const float* __restrict__ g1, const float* __restrict__ be1,
    const float* __restrict__ g2, const float* __restrict__ be2)
{
    __shared__ float sred[4];
    int row = blockIdx.x;
    int s = row % 3;
    const float* g  = (s == 0) ? g0 : (s == 1) ? g1 : g2;
    const float* be = (s == 0) ? be0 : (s == 1) ? be1 : be2;
    __half* xr = x + (size_t)row * 512;
    int t = threadIdx.x;
    union { uint2 u; __half2 h[2]; } pk;
    pk.u = *reinterpret_cast<const uint2*>(xr + 4 * t);
    float2 f0 = __half22float2(pk.h[0]), f1 = __half22float2(pk.h[1]);
    float sum = blockSum128(f0.x + f0.y + f1.x + f1.y, sred);
    float mean = sum * (1.f / 512.f);
    float dx = f0.x - mean, dy = f0.y - mean, dz = f1.x - mean, dw = f1.y - mean;
    float ss = blockSum128(dx * dx + dy * dy + dz * dz + dw * dw, sred);
    float rstd = rsqrtf(ss * (1.f / 512.f) + 1e-5f);
    float4 gv = reinterpret_cast<const float4*>(g)[t];
    float4 bv = reinterpret_cast<const float4*>(be)[t];
    float ox = fmaxf(dx * rstd * gv.x + bv.x, 0.f);
    float oy = fmaxf(dy * rstd * gv.y + bv.y, 0.f);
    float oz = fmaxf(dz * rstd * gv.z + bv.z, 0.f);
    float ow = fmaxf(dw * rstd * gv.w + bv.w, 0.f);
    pk.h[0] = __floats2half2_rn(ox, oy);
    pk.h[1] = __floats2half2_rn(oz, ow);
    *reinterpret_cast<uint2*>(xr + 4 * t) = pk.u;
}

// 3-token, 8-head attention on fp16 qkv; one warp per (sample, head)
__global__ void __launch_bounds__(128) attn3_h(
    const __half* __restrict__ qkv, __half* __restrict__ ctx)
{
    int warp = blockIdx.x * 4 + (threadIdx.x >> 5);
    int lane = threadIdx.x & 31;
    int b = warp >> 3, h = warp & 7;
    const __half* base = qkv + (size_t)b * 4608 + h * 64 + 2 * lane;
    float2 q[3], k[3], v[3];
#pragma unroll
    for (int t = 0; t < 3; t++) {
        q[t] = __half22float2(*reinterpret_cast<const __half2*>(base + t * 1536));
        k[t] = __half22float2(*reinterpret_cast<const __half2*>(base + t * 1536 + 512));
        v[t] = __half22float2(*reinterpret_cast<const __half2*>(base + t * 1536 + 1024));
    }
    float a[3][3];
#pragma unroll
    for (int i = 0; i < 3; i++)
#pragma unroll
        for (int j = 0; j < 3; j++) {
            float p = q[i].x * k[j].x + q[i].y * k[j].y;
            a[i][j] = warpSum(p) * 0.125f;
        }
#pragma unroll
    for (int i = 0; i < 3; i++) {
        float m = fmaxf(a[i][0], fmaxf(a[i][1], a[i][2]));
        float e0 = expf(a[i][0] - m), e1 = expf(a[i][1] - m), e2 = expf(a[i][2] - m);
        float inv = 1.f / (e0 + e1 + e2);
        a[i][0] = e0 * inv; a[i][1] = e1 * inv; a[i][2] = e2 * inv;
    }
#pragma unroll
    for (int i = 0; i < 3; i++) {
        float ox = a[i][0] * v[0].x + a[i][1] * v[1].x + a[i][2] * v[2].x;
        float oy = a[i][0] * v[0].y + a[i][1] * v[1].y + a[i][2] * v[2].y;
        *reinterpret_cast<__half2*>(ctx + (size_t)(b * 3 + i) * 512 + h * 64 + 2 * lane)
            = __floats2half2_rn(ox, oy);
    }
}

// gate logits + softmax + weighted fuse (fp16 gh/att) -> fp16 fused + f32 gate
__global__ void __launch_bounds__(128) gate_fuse_h(
    const __half* __restrict__ gh, const float* __restrict__ gw2,
    const float* __restrict__ gb2, const __half* __restrict__ att,
    __half* __restrict__ fused, float* __restrict__ gate_out)
{
    __shared__ float sred[4];
    int b = blockIdx.x, t = threadIdx.x;
    union { uint2 u; __half2 h[2]; } hv;
    hv.u = *reinterpret_cast<const uint2*>(gh + (size_t)b * 512 + 4 * t);
    float2 h0 = __half22float2(hv.h[0]), h1 = __half22float2(hv.h[1]);
    float l[3];
#pragma unroll
    for (int s = 0; s < 3; s++) {
        float4 w = reinterpret_cast<const float4*>(gw2 + s * 512)[t];
        l[s] = blockSum128(h0.x * w.x + h0.y * w.y + h1.x * w.z + h1.y * w.w, sred)
             + gb2[s];
    }
    float m = fmaxf(l[0], fmaxf(l[1], l[2]));
    float e0 = expf(l[0] - m), e1 = expf(l[1] - m), e2 = expf(l[2] - m);
    float inv = 1.f / (e0 + e1 + e2);
    float w0 = e0 * inv, w1 = e1 * inv, w2 = e2 * inv;
    if (t == 0) {
        gate_out[b * 3 + 0] = w0;
        gate_out[b * 3 + 1] = w1;
        gate_out[b * 3 + 2] = w2;
    }
    const __half* ab = att + (size_t)b * 1536 + 4 * t;
    union { uint2 u; __half2 h[2]; } x0, x1, x2;
    x0.u = *reinterpret_cast<const uint2*>(ab);
    x1.u = *reinterpret_cast<const uint2*>(ab + 512);
    x2.u = *reinterpret_cast<const uint2*>(ab + 1024);
    float2 a0 = __half22float2(x0.h[0]), b0f = __half22float2(x0.h[1]);
    float2 a1 = __half22float2(x1.h[0]), b1f = __half22float2(x1.h[1]);
    float2 a2 = __half22float2(x2.h[0]), b2f = __half22float2(x2.h[1]);
    union { uint2 u; __half2 h[2]; } pk;
    pk.h[0] = __floats2half2_rn(w0 * a0.x + w1 * a1.x + w2 * a2.x,
                                w0 * a0.y + w1 * a1.y + w2 * a2.y);
    pk.h[1] = __floats2half2_rn(w0 * b0f.x + w1 * b1f.x + w2 * b2f.x,
                                w0 * b0f.y + w1 * b1f.y + w2 * b2f.y);
    *reinterpret_cast<uint2*>(fused + (size_t)b * 512 + 4 * t) = pk.u;
}

// classifier head: LN(256) + ReLU + 6-way linear; one warp per sample
__global__ void __launch_bounds__(128) cls_head(
    const float* __restrict__ chid, const float* __restrict__ cg,
    const float* __restrict__ cbeta, const float* __restrict__ cw2,
    const float* __restrict__ cb2, float* __restrict__ logits)
{
    int b = blockIdx.x * 4 + (threadIdx.x >> 5);
    int lane = threadIdx.x & 31;
    const float* hr = chid + (size_t)b * 256;
    float4 h0 = reinterpret_cast<const float4*>(hr)[lane];
    float4 h1 = reinterpret_cast<const float4*>(hr)[lane + 32];
    float sum = warpSum(h0.x + h0.y + h0.z + h0.w + h1.x + h1.y + h1.z + h1.w);
    float mean = sum * (1.f / 256.f);
    h0.x -= mean; h0.y -= mean; h0.z -= mean; h0.w -= mean;
    h1.x -= mean; h1.y -= mean; h1.z -= mean; h1.w -= mean;
    float ss = warpSum(h0.x * h0.x + h0.y * h0.y + h0.z * h0.z + h0.w * h0.w
                     + h1.x * h1.x + h1.y * h1.y + h1.z * h1.z + h1.w * h1.w);
    float rstd = rsqrtf(ss * (1.f / 256.f) + 1e-5f);
    float4 cg0 = reinterpret_cast<const float4*>(cg)[lane];
    float4 cg1 = reinterpret_cast<const float4*>(cg)[lane + 32];
    float4 cb0 = reinterpret_cast<const float4*>(cbeta)[lane];
    float4 cb1 = reinterpret_cast<const float4*>(cbeta)[lane + 32];
    h0.x = fmaxf(h0.x * rstd * cg0.x + cb0.x, 0.f);
    h0.y = fmaxf(h0.y * rstd * cg0.y + cb0.y, 0.f);
    h0.z = fmaxf(h0.z * rstd * cg0.z + cb0.z, 0.f);
    h0.w = fmaxf(h0.w * rstd * cg0.w + cb0.w, 0.f);
    h1.x = fmaxf(h1.x * rstd * cg1.x + cb1.x, 0.f);
    h1.y = fmaxf(h1.y * rstd * cg1.y + cb1.y, 0.f);
    h1.z = fmaxf(h1.z * rstd * cg1.z + cb1.z, 0.f);
    h1.w = fmaxf(h1.w * rstd * cg1.w + cb1.w, 0.f);
#pragma unroll
    for (int c = 0; c < 6; c++) {
        const float4* wr = reinterpret_cast<const float4*>(cw2 + c * 256);
        float4 w0 = wr[lane], w1 = wr[lane + 32];
        float p = h0.x * w0.x + h0.y * w0.y + h0.z * w0.z + h0.w * w0.w
                + h1.x * w1.x + h1.y * w1.y + h1.z * w1.z + h1.w * w1.w;
        p = warpSum(p);
        if (lane == 0) logits[(size_t)b * 6 + c] = p + cb2[c];
    }
}

// ---------------------------------------------------------------------------
extern "C" void kernel_launch(void* const* d_in, const int* in_sizes, int n_in,
                              void* d_out, int out_size)
{
    const float* rgb       = (const float*)d_in[0];
    const float* pose      = (const float*)d_in[1];
    const float* flow      = (const float*)d_in[2];
    const float* rgb_w     = (const float*)d_in[3];
    const float* rgb_b     = (const float*)d_in[4];
    const float* rgb_g     = (const float*)d_in[5];
    const float* rgb_beta  = (const float*)d_in[6];
    const float* pose_w    = (const float*)d_in[7];
    const float* pose_b    = (const float*)d_in[8];
    const float* pose_g    = (const float*)d_in[9];
    const float* pose_beta = (const float*)d_in[10];
    const float* flow_w    = (const float*)d_in[11];
    const float* flow_b    = (const float*)d_in[12];
    const float* flow_g    = (const float*)d_in[13];
    const float* flow_beta = (const float*)d_in[14];
    const float* in_w      = (const float*)d_in[15];
    const float* in_b      = (const float*)d_in[16];
    const float* out_w     = (const float*)d_in[17];
    const float* out_b     = (const float*)d_in[18];
    const float* gw1       = (const float*)d_in[19];
    const float* gb1       = (const float*)d_in[20];
    const float* gw2       = (const float*)d_in[21];
    const float* gb2       = (const float*)d_in[22];
    const float* cw1       = (const float*)d_in[23];
    const float* cb1       = (const float*)d_in[24];
    const float* cg        = (const float*)d_in[25];
    const float* cbeta     = (const float*)d_in[26];
    const float* cw2       = (const float*)d_in[27];
    const float* cb2       = (const float*)d_in[28];

    float* out = (float*)d_out;                 // [B*6 logits | B*3 gate]
    float* logits_out = out;
    float* gate_out   = out + (size_t)BATCH * 6;

    __half *rgb_h, *pose_h, *flow_h, *proj_h, *qkv_h, *ctx_h, *att_h, *gh_h, *fused_h;
    __half *rgbw_h, *posew_h, *floww_h, *inw_h, *outw_h, *gw1_h, *cw1_h;
    float *chid;
    cudaGetSymbolAddress((void**)&rgb_h,   g_rgb_h);
    cudaGetSymbolAddress((void**)&pose_h,  g_pose_h);
    cudaGetSymbolAddress((void**)&flow_h,  g_flow_h);
    cudaGetSymbolAddress((void**)&proj_h,  g_proj_h);
    cudaGetSymbolAddress((void**)&qkv_h,   g_qkv_h);
    cudaGetSymbolAddress((void**)&ctx_h,   g_ctx_h);
    cudaGetSymbolAddress((void**)&att_h,   g_att_h);
    cudaGetSymbolAddress((void**)&gh_h,    g_gh_h);
    cudaGetSymbolAddress((void**)&fused_h, g_fused_h);
    cudaGetSymbolAddress((void**)&rgbw_h,  g_rgbw_h);
    cudaGetSymbolAddress((void**)&posew_h, g_posew_h);
    cudaGetSymbolAddress((void**)&floww_h, g_floww_h);
    cudaGetSymbolAddress((void**)&inw_h,   g_inw_h);
    cudaGetSymbolAddress((void**)&outw_h,  g_outw_h);
    cudaGetSymbolAddress((void**)&gw1_h,   g_gw1_h);
    cudaGetSymbolAddress((void**)&cw1_h,   g_cw1_h);
    cudaGetSymbolAddress((void**)&chid, g_chid);

    cudaFuncSetAttribute((const void*)gemm_w<0, __half>,
        cudaFuncAttributeMaxDynamicSharedMemorySize, W_SMEM);
    cudaFuncSetAttribute((const void*)gemm_w<1, __half>,
        cudaFuncAttributeMaxDynamicSharedMemorySize, W_SMEM);
    cudaFuncSetAttribute((const void*)gemm_w<0, float>,
        cudaFuncAttributeMaxDynamicSharedMemorySize, W_SMEM);

    // 0) one fused fp32 -> fp16 convert (inputs + GEMM weights)
    {
        CvtArgs ca;
        ca.src[0] = rgb;    ca.dst[0] = rgb_h;
        ca.src[1] = pose;   ca.dst[1] = pose_h;
        ca.src[2] = flow;   ca.dst[2] = flow_h;
        ca.src[3] = rgb_w;  ca.dst[3] = rgbw_h;
        ca.src[4] = pose_w; ca.dst[4] = posew_h;
        ca.src[5] = flow_w; ca.dst[5] = floww_h;
        ca.src[6] = in_w;   ca.dst[6] = inw_h;
        ca.src[7] = out_w;  ca.dst[7] = outw_h;
        ca.src[8] = gw1;    ca.dst[8] = gw1_h;
        ca.src[9] = cw1;    ca.dst[9] = cw1_h;
        f2h_all<<<(unsigned)((CVT_TOTAL8 + 255) / 256), 256>>>(ca);
    }

    // 1) per-modality projections -> stacked/concat fp16 buffer (B,3,512)
    gemm_w<0, __half><<<dim3(2, 128), 256, W_SMEM>>>(rgb_h,  rgbw_h,  rgb_b,  proj_h + 0,    768,  1536);
    gemm_w<0, __half><<<dim3(2, 128), 256, W_SMEM>>>(pose_h, posew_h, pose_b, proj_h + 512,  640,  1536);
    gemm_w<0, __half><<<dim3(2, 128), 256, W_SMEM>>>(flow_h, floww_h, flow_b, proj_h + 1024, 1024, 1536);
    // 2) LN + ReLU per (b, modality) row (in-place fp16)
    ln_relu3_h<<<BATCH * 3, 128>>>(proj_h, rgb_g, rgb_beta, pose_g, pose_beta,
                                   flow_g, flow_beta);
    // 3) packed QKV projection: (49152 x 512) x (1536 x 512)^T -> (49152,1536)
    gemm_w<0, __half><<<dim3(6, 384), 256, W_SMEM>>>(proj_h, inw_h, in_b, qkv_h, 512, 1536);
    // 4) 3-token 8-head attention -> fp16 ctx
    attn3_h<<<BATCH * 8 / 4, 128>>>(qkv_h, ctx_h);
    // 5) attention out-projection -> fp16 att
    gemm_w<0, __half><<<dim3(2, 384), 256, W_SMEM>>>(ctx_h, outw_h, out_b, att_h, 512, 512);
    // 6) gate MLP layer 1 (proj_h as (B,1536) concat) + ReLU -> fp16 gh
    gemm_w<1, __half><<<dim3(2, 128), 256, W_SMEM>>>(proj_h, gw1_h, gb1, gh_h, 1536, 512);
    // 7) gate logits + softmax + weighted fusion -> fp16 fused + gate out
    gate_fuse_h<<<BATCH, 128>>>(gh_h, gw2, gb2, att_h, fused_h, gate_out);
    // 8) classifier layer 1 -> fp32 chid
    gemm_w<0, float><<<dim3(1, 128), 256, W_SMEM>>>(fused_h, cw1_h, cb1, chid, 512, 256);
    // 9) LN + ReLU + 6-way head
    cls_head<<<BATCH / 4, 128>>>(chid, cg, cbeta, cw2, cb2, logits_out);
}

// round 7
// speedup vs baseline: 1.1880x; 1.1880x over previous
#include <cuda_runtime.h>
#include <cuda_fp16.h>
#include <cstdint>
#include <math.h>

// ---------------------------------------------------------------------------
// AttentionFusion on GB300 (sm_103): fp16 mma.sync (m16n8k16) GEMMs via
// ldmatrix, 128x128 CTA tile / 2 CTAs/SM, fp16 activation chain.
// B=16384, E=512, H=8, HD=64, NC=6.
// ---------------------------------------------------------------------------

#define BATCH 16384

// fp16 scratch
__device__ __half g_rgb_h [BATCH * 768];
__device__ __half g_pose_h[BATCH * 640];
__device__ __half g_flow_h[BATCH * 1024];
__device__ __half g_proj_h[BATCH * 1536];   // (B,3,512), post-LN in-place
__device__ __half g_qkv_h [BATCH * 4608];   // (B*3, 1536) rows
__device__ __half g_ctx_h [BATCH * 1536];
__device__ __half g_att_h [BATCH * 1536];
__device__ __half g_gh_h  [BATCH * 512];
__device__ __half g_fused_h[BATCH * 512];
// fp16 weights
__device__ __half g_rgbw_h [512 * 768];
__device__ __half g_posew_h[512 * 640];
__device__ __half g_floww_h[512 * 1024];
__device__ __half g_inw_h  [1536 * 512];
__device__ __half g_outw_h [512 * 512];
__device__ __half g_gw1_h  [512 * 1536];
__device__ __half g_cw1_h  [256 * 512];
// fp32 scratch
__device__ float g_chid[BATCH * 256];

__device__ __forceinline__ uint32_t smem_u32(const void* p) {
    uint32_t a;
    asm("{ .reg .u64 t; cvta.to.shared.u64 t, %1; cvt.u32.u64 %0, t; }"
        : "=r"(a) : "l"(p));
    return a;
}

// ---------------------------------------------------------------------------
// single fused fp32->fp16 convert over all inputs+weights
// ---------------------------------------------------------------------------
struct CvtArgs {
    const float* src[10];
    __half* dst[10];
};
__device__ __constant__ const long CVT_END[10] = {
    12582912,              // rgb     16384*768
    23068672,              // pose    +16384*640
    39845888,              // flow    +16384*1024
    40239104,              // rgbw    +512*768
    40566784,              // posew   +512*640
    41091072,              // floww   +512*1024
    41877504,              // inw     +1536*512
    42139648,              // outw    +512*512
    42926080,              // gw1     +512*1536
    43057152               // cw1     +256*512
};
constexpr long CVT_TOTAL8 = 43057152 / 8;

__global__ void __launch_bounds__(256) f2h_all(CvtArgs args)
{
    long v = (long)blockIdx.x * 256 + threadIdx.x;
    if (v >= CVT_TOTAL8) return;
    long i = v * 8;
    int s = 0;
#pragma unroll
    for (int k = 0; k < 10; k++)
        if (i >= CVT_END[k]) s = k + 1;
    long base = (s == 0) ? 0 : CVT_END[s - 1];
    long off = i - base;
    const float* in = args.src[s] + off;
    __half* out = args.dst[s] + off;
    float4 v0 = *reinterpret_cast<const float4*>(in);
    float4 v1 = *reinterpret_cast<const float4*>(in + 4);
    union { uint4 u; __half2 h[4]; } pk;
    pk.h[0] = __floats2half2_rn(v0.x, v0.y);
    pk.h[1] = __floats2half2_rn(v0.z, v0.w);
    pk.h[2] = __floats2half2_rn(v1.x, v1.y);
    pk.h[3] = __floats2half2_rn(v1.z, v1.w);
    *reinterpret_cast<uint4*>(out) = pk.u;
}

// ---------------------------------------------------------------------------
// fp16 tensor-core GEMM: C[M,N] = A[M,K] * W[N,K]^T + bias (torch Linear)
// BM=BN=128, BK=64 halves, 256 threads = 8 warps (4m x 2n), warp tile 32x64.
// 3-stage cp.async pipeline, SW128-swizzled smem, ldmatrix.x4 fragments,
// mma.m16n8k16.f32.f16, 2 CTAs/SM.  Requires M%128==0, N%128==0, K%64==0,
// K>=192.
// ---------------------------------------------------------------------------
constexpr int H_STAGEB = 32768;               // bytes per stage (A 16K + B 16K)
constexpr int H_SMEM   = 3 * H_STAGEB;        // 98304

__device__ __forceinline__ void storePair(float v0, float v1, __half* p) {
    *reinterpret_cast<__half2*>(p) = __floats2half2_rn(v0, v1);
}
__device__ __forceinline__ void storePair(float v0, float v1, float* p) {
    *reinterpret_cast<float2*>(p) = make_float2(v0, v1);
}

template<int RELU, typename OT>
__global__ void __launch_bounds__(256, 2) gemm_h(
    const __half* __restrict__ A, const __half* __restrict__ W,
    const float* __restrict__ bias, OT* __restrict__ C,
    int K, int ldc)
{
    extern __shared__ __align__(16) char smem[];
    const uint32_t sb = smem_u32(smem);
    const int tid = threadIdx.x;
    const int wid = tid >> 5, lane = tid & 31;
    const int q  = lane >> 2, kr = lane & 3;
    const int wm = wid & 3,  wn = wid >> 2;
    const int bm = blockIdx.y * 128, bn = blockIdx.x * 128;

    // cp.async: thread covers 64B (4 x 16B segs) of one 128B row, A and B
    const int lrow = tid >> 1;
    const int hoff = (tid & 1) * 32;               // halves
    const __half* Arow = A + (size_t)(bm + lrow) * K + hoff;
    const __half* Wrow = W + (size_t)(bn + lrow) * K + hoff;
    uint32_t dstA[4];
    {
        const uint32_t rowb = (uint32_t)lrow * 128;
        const uint32_t m = (lrow & 7) << 4;
#pragma unroll
        for (int i = 0; i < 4; i++) {
            const uint32_t seg = (tid & 1) * 4 + i;
            dstA[i] = sb + rowb + ((seg * 16) ^ m);
        }
    }

#define LOAD_CHUNK(kc_) do {                                                  \
        const uint32_t st_ = ((kc_) % 3) * H_STAGEB;                          \
        const __half* ap_ = Arow + (size_t)(kc_) * 64;                        \
        const __half* wp_ = Wrow + (size_t)(kc_) * 64;                        \
        _Pragma("unroll")                                                     \
        for (int i = 0; i < 4; i++)                                           \
            asm volatile("cp.async.cg.shared.global [%0], [%1], 16;"          \
                :: "r"(dstA[i] + st_), "l"(ap_ + i * 8) : "memory");          \
        _Pragma("unroll")                                                     \
        for (int i = 0; i < 4; i++)                                           \
            asm volatile("cp.async.cg.shared.global [%0], [%1], 16;"          \
                :: "r"(dstA[i] + st_ + 16384), "l"(wp_ + i * 8) : "memory");  \
        asm volatile("cp.async.commit_group;" ::: "memory");                  \
    } while (0)

    const int KC = K >> 6;
    LOAD_CHUNK(0); LOAD_CHUNK(1); LOAD_CHUNK(2);

    // ldmatrix address components (per thread)
    uint32_t rowbA[2], mAr[2], rowbB[4], mBr[4];
    const uint32_t colA0 = (lane >> 4) * 16;             // bytes
    const uint32_t colB0 = ((lane >> 3) & 1) * 16;       // bytes
#pragma unroll
    for (int t = 0; t < 2; t++) {
        const uint32_t r = wm * 32 + t * 16 + (lane & 15);
        rowbA[t] = r * 128; mAr[t] = (r & 7) << 4;
    }
#pragma unroll
    for (int jj = 0; jj < 4; jj++) {
        const uint32_t r = wn * 64 + jj * 16 + (lane & 7) + ((lane >> 4) & 1) * 8;
        rowbB[jj] = r * 128; mBr[jj] = (r & 7) << 4;
    }

    float c[2][8][4];
#pragma unroll
    for (int t = 0; t < 2; t++)
#pragma unroll
        for (int j = 0; j < 8; j++)
#pragma unroll
            for (int r = 0; r < 4; r++) c[t][j][r] = 0.f;

    for (int kc = 0; kc < KC; kc++) {
        asm volatile("cp.async.wait_group 2;" ::: "memory");
        __syncthreads();
        const uint32_t As = sb + (kc % 3) * H_STAGEB;
        const uint32_t Bs = As + 16384;
#pragma unroll
        for (int ks = 0; ks < 4; ks++) {
            uint32_t a[2][4], b[4][4];
#pragma unroll
            for (int t = 0; t < 2; t++) {
                const uint32_t ad = As + rowbA[t] + ((colA0 + ks * 32) ^ mAr[t]);
                asm volatile(
                    "ldmatrix.sync.aligned.m8n8.x4.shared.b16 {%0,%1,%2,%3}, [%4];"
                    : "=r"(a[t][0]), "=r"(a[t][1]), "=r"(a[t][2]), "=r"(a[t][3])
                    : "r"(ad));
            }
#pragma unroll
            for (int jj = 0; jj < 4; jj++) {
                const uint32_t bd = Bs + rowbB[jj] + ((colB0 + ks * 32) ^ mBr[jj]);
                asm volatile(
                    "ldmatrix.sync.aligned.m8n8.x4.shared.b16 {%0,%1,%2,%3}, [%4];"
                    : "=r"(b[jj][0]), "=r"(b[jj][1]), "=r"(b[jj][2]), "=r"(b[jj][3])
                    : "r"(bd));
            }
#pragma unroll
            for (int t = 0; t < 2; t++)
#pragma unroll
                for (int j = 0; j < 8; j++) {
                    const int jj = j >> 1, lo = (j & 1) * 2;
                    asm volatile(
                        "mma.sync.aligned.m16n8k16.row.col.f32.f16.f16.f32 "
                        "{%0,%1,%2,%3}, {%4,%5,%6,%7}, {%8,%9}, {%0,%1,%2,%3};"
                        : "+f"(c[t][j][0]), "+f"(c[t][j][1]),
                          "+f"(c[t][j][2]), "+f"(c[t][j][3])
                        : "r"(a[t][0]), "r"(a[t][1]), "r"(a[t][2]), "r"(a[t][3]),
                          "r"(b[jj][lo]), "r"(b[jj][lo + 1]));
                }
        }
        __syncthreads();
        const int kn = kc + 3;
        if (kn < KC) { LOAD_CHUNK(kn); }
        else asm volatile("cp.async.commit_group;" ::: "memory");
    }
#undef LOAD_CHUNK

    // epilogue: bias (+ReLU)
#pragma unroll
    for (int t = 0; t < 2; t++) {
        const int r0 = bm + wm * 32 + t * 16 + q;
#pragma unroll
        for (int j = 0; j < 8; j++) {
            const int col = bn + wn * 64 + j * 8 + (kr << 1);
            const float b0 = bias[col], b1 = bias[col + 1];
            float v00 = c[t][j][0] + b0, v01 = c[t][j][1] + b1;
            float v10 = c[t][j][2] + b0, v11 = c[t][j][3] + b1;
            if (RELU) {
                v00 = fmaxf(v00, 0.f); v01 = fmaxf(v01, 0.f);
                v10 = fmaxf(v10, 0.f); v11 = fmaxf(v11, 0.f);
            }
            storePair(v00, v01, C + (size_t)r0 * ldc + col);
            storePair(v10, v11, C + (size_t)(r0 + 8) * ldc + col);
        }
    }
}

// ---------------------------------------------------------------------------
// elementwise / small kernels
// ---------------------------------------------------------------------------
__device__ __forceinline__ float warpSum(float v) {
#pragma unroll
    for (int o = 16; o > 0; o >>= 1) v += __shfl_xor_sync(0xffffffffu, v, o);
    return v;
}

__device__ __forceinline__ float blockSum128(float v, float* sred) {
    int lane = threadIdx.x & 31, w = threadIdx.x >> 5;
    v = warpSum(v);
    __syncthreads();
    if (lane == 0) sred[w] = v;
    __syncthreads();
    return sred[0] + sred[1] + sred[2] + sred[3];
}

// in-place LN+ReLU on fp16 rows of 512; modality = row % 3
__global__ void __launch_bounds__(128) ln_relu3_h(
    __half* __restrict__ x,
    const float* __restrict__ g0, const float* __restrict__ be0,
    const float* __restrict__ g1, const float* __restrict__ be1,
    const float* __restrict__ g2, const float* __restrict__ be2)
{
    __shared__ float sred[4];
    int row = blockIdx.x;
    int s = row % 3;
    const float* g  = (s == 0) ? g0 : (s == 1) ? g1 : g2;
    const float* be = (s == 0) ? be0 : (s == 1) ? be1 : be2;
    __half* xr = x + (size_t)row * 512;
    int t = threadIdx.x;
    union { uint2 u; __half2 h[2]; } pk;
    pk.u = *reinterpret_cast<const uint2*>(xr + 4 * t);
    float2 f0 = __half22float2(pk.h[0]), f1 = __half22float2(pk.h[1]);
    float sum = blockSum128(f0.x + f0.y + f1.x + f1.y, sred);
    float mean = sum * (1.f / 512.f);
    float dx = f0.x - mean, dy = f0.y - mean, dz = f1.x - mean, dw = f1.y - mean;
    float ss = blockSum128(dx * dx + dy * dy + dz * dz + dw * dw, sred);
    float rstd = rsqrtf(ss * (1.f / 512.f) + 1e-5f);
    float4 gv = reinterpret_cast<const float4*>(g)[t];
    float4 bv = reinterpret_cast<const float4*>(be)[t];
    float ox = fmaxf(dx * rstd * gv.x + bv.x, 0.f);
    float oy = fmaxf(dy * rstd * gv.y + bv.y, 0.f);
    float oz = fmaxf(dz * rstd * gv.z + bv.z, 0.f);
    float ow = fmaxf(dw * rstd * gv.w + bv.w, 0.f);
    pk.h[0] = __floats2half2_rn(ox, oy);
    pk.h[1] = __floats2half2_rn(oz, ow);
    *reinterpret_cast<uint2*>(xr + 4 * t) = pk.u;
}

// 3-token, 8-head attention on fp16 qkv; one warp per (sample, head)
__global__ void __launch_bounds__(128) attn3_h(
    const __half* __restrict__ qkv, __half* __restrict__ ctx)
{
    int warp = blockIdx.x * 4 + (threadIdx.x >> 5);
    int lane = threadIdx.x & 31;
    int b = warp >> 3, h = warp & 7;
    const __half* base = qkv + (size_t)b * 4608 + h * 64 + 2 * lane;
    float2 q[3], k[3], v[3];
#pragma unroll
    for (int t = 0; t < 3; t++) {
        q[t] = __half22float2(*reinterpret_cast<const __half2*>(base + t * 1536));
        k[t] = __half22float2(*reinterpret_cast<const __half2*>(base + t * 1536 + 512));
        v[t] = __half22float2(*reinterpret_cast<const __half2*>(base + t * 1536 + 1024));
    }
    float a[3][3];
#pragma unroll
    for (int i = 0; i < 3; i++)
#pragma unroll
        for (int j = 0; j < 3; j++) {
            float p = q[i].x * k[j].x + q[i].y * k[j].y;
            a[i][j] = warpSum(p) * 0.125f;
        }
#pragma unroll
    for (int i = 0; i < 3; i++) {
        float m = fmaxf(a[i][0], fmaxf(a[i][1], a[i][2]));
        float e0 = expf(a[i][0] - m), e1 = expf(a[i][1] - m), e2 = expf(a[i][2] - m);
        float inv = 1.f / (e0 + e1 + e2);
        a[i][0] = e0 * inv; a[i][1] = e1 * inv; a[i][2] = e2 * inv;
    }
#pragma unroll
    for (int i = 0; i < 3; i++) {
        float ox = a[i][0] * v[0].x + a[i][1] * v[1].x + a[i][2] * v[2].x;
        float oy = a[i][0] * v[0].y + a[i][1] * v[1].y + a[i][2] * v[2].y;
        *reinterpret_cast<__half2*>(ctx + (size_t)(b * 3 + i) * 512 + h * 64 + 2 * lane)
            = __floats2half2_rn(ox, oy);
    }
}

// gate logits + softmax + weighted fuse (fp16 gh/att) -> fp16 fused + f32 gate
__global__ void __launch_bounds__(128) gate_fuse_h(
    const __half* __restrict__ gh, const float* __restrict__ gw2,
    const float* __restrict__ gb2, const __half* __restrict__ att,
    __half* __restrict__ fused, float* __restrict__ gate_out)
{
    __shared__ float sred[4];
    int b = blockIdx.x, t = threadIdx.x;
    union { uint2 u; __half2 h[2]; } hv;
    hv.u = *reinterpret_cast<const uint2*>(gh + (size_t)b * 512 + 4 * t);
    float2 h0 = __half22float2(hv.h[0]), h1 = __half22float2(hv.h[1]);
    float l[3];
#pragma unroll
    for (int s = 0; s < 3; s++) {
        float4 w = reinterpret_cast<const float4*>(gw2 + s * 512)[t];
        l[s] = blockSum128(h0.x * w.x + h0.y * w.y + h1.x * w.z + h1.y * w.w, sred)
             + gb2[s];
    }
    float m = fmaxf(l[0], fmaxf(l[1], l[2]));
    float e0 = expf(l[0] - m), e1 = expf(l[1] - m), e2 = expf(l[2] - m);
    float inv = 1.f / (e0 + e1 + e2);
    float w0 = e0 * inv, w1 = e1 * inv, w2 = e2 * inv;
    if (t == 0) {
        gate_out[b * 3 + 0] = w0;
        gate_out[b * 3 + 1] = w1;
        gate_out[b * 3 + 2] = w2;
    }
    const __half* ab = att + (size_t)b * 1536 + 4 * t;
    union { uint2 u; __half2 h[2]; } x0, x1, x2;
    x0.u = *reinterpret_cast<const uint2*>(ab);
    x1.u = *reinterpret_cast<const uint2*>(ab + 512);
    x2.u = *reinterpret_cast<const uint2*>(ab + 1024);
    float2 a0 = __half22float2(x0.h[0]), b0f = __half22float2(x0.h[1]);
    float2 a1 = __half22float2(x1.h[0]), b1f = __half22float2(x1.h[1]);
    float2 a2 = __half22float2(x2.h[0]), b2f = __half22float2(x2.h[1]);
    union { uint2 u; __half2 h[2]; } pk;
    pk.h[0] = __floats2half2_rn(w0 * a0.x + w1 * a1.x + w2 * a2.x,
                                w0 * a0.y + w1 * a1.y + w2 * a2.y);
    pk.h[1] = __floats2half2_rn(w0 * b0f.x + w1 * b1f.x + w2 * b2f.x,
                                w0 * b0f.y + w1 * b1f.y + w2 * b2f.y);
    *reinterpret_cast<uint2*>(fused + (size_t)b * 512 + 4 * t) = pk.u;
}

// classifier head: LN(256) + ReLU + 6-way linear; one warp per sample
__global__ void __launch_bounds__(128) cls_head(
    const float* __restrict__ chid, const float* __restrict__ cg,
    const float* __restrict__ cbeta, const float* __restrict__ cw2,
    const float* __restrict__ cb2, float* __restrict__ logits)
{
    int b = blockIdx.x * 4 + (threadIdx.x >> 5);
    int lane = threadIdx.x & 31;
    const float* hr = chid + (size_t)b * 256;
    float4 h0 = reinterpret_cast<const float4*>(hr)[lane];
    float4 h1 = reinterpret_cast<const float4*>(hr)[lane + 32];
    float sum = warpSum(h0.x + h0.y + h0.z + h0.w + h1.x + h1.y + h1.z + h1.w);
    float mean = sum * (1.f / 256.f);
    h0.x -= mean; h0.y -= mean; h0.z -= mean; h0.w -= mean;
    h1.x -= mean; h1.y -= mean; h1.z -= mean; h1.w -= mean;
    float ss = warpSum(h0.x * h0.x + h0.y * h0.y + h0.z * h0.z + h0.w * h0.w
                     + h1.x * h1.x + h1.y * h1.y + h1.z * h1.z + h1.w * h1.w);
    float rstd = rsqrtf(ss * (1.f / 256.f) + 1e-5f);
    float4 cg0 = reinterpret_cast<const float4*>(cg)[lane];
    float4 cg1 = reinterpret_cast<const float4*>(cg)[lane + 32];
    float4 cb0 = reinterpret_cast<const float4*>(cbeta)[lane];
    float4 cb1 = reinterpret_cast<const float4*>(cbeta)[lane + 32];
    h0.x = fmaxf(h0.x * rstd * cg0.x + cb0.x, 0.f);
    h0.y = fmaxf(h0.y * rstd * cg0.y + cb0.y, 0.f);
    h0.z = fmaxf(h0.z * rstd * cg0.z + cb0.z, 0.f);
    h0.w = fmaxf(h0.w * rstd * cg0.w + cb0.w, 0.f);
    h1.x = fmaxf(h1.x * rstd * cg1.x + cb1.x, 0.f);
    h1.y = fmaxf(h1.y * rstd * cg1.y + cb1.y, 0.f);
    h1.z = fmaxf(h1.z * rstd * cg1.z + cb1.z, 0.f);
    h1.w = fmaxf(h1.w * rstd * cg1.w + cb1.w, 0.f);
#pragma unroll
    for (int c = 0; c < 6; c++) {
        const float4* wr = reinterpret_cast<const float4*>(cw2 + c * 256);
        float4 w0 = wr[lane], w1 = wr[lane + 32];
        float p = h0.x * w0.x + h0.y * w0.y + h0.z * w0.z + h0.w * w0.w
                + h1.x * w1.x + h1.y * w1.y + h1.z * w1.z + h1.w * w1.w;
        p = warpSum(p);
        if (lane == 0) logits[(size_t)b * 6 + c] = p + cb2[c];
    }
}

// ---------------------------------------------------------------------------
extern "C" void kernel_launch(void* const* d_in, const int* in_sizes, int n_in,
                              void* d_out, int out_size)
{
    const float* rgb       = (const float*)d_in[0];
    const float* pose      = (const float*)d_in[1];
    const float* flow      = (const float*)d_in[2];
    const float* rgb_w     = (const float*)d_in[3];
    const float* rgb_b     = (const float*)d_in[4];
    const float* rgb_g     = (const float*)d_in[5];
    const float* rgb_beta  = (const float*)d_in[6];
    const float* pose_w    = (const float*)d_in[7];
    const float* pose_b    = (const float*)d_in[8];
    const float* pose_g    = (const float*)d_in[9];
    const float* pose_beta = (const float*)d_in[10];
    const float* flow_w    = (const float*)d_in[11];
    const float* flow_b    = (const float*)d_in[12];
    const float* flow_g    = (const float*)d_in[13];
    const float* flow_beta = (const float*)d_in[14];
    const float* in_w      = (const float*)d_in[15];
    const float* in_b      = (const float*)d_in[16];
    const float* out_w     = (const float*)d_in[17];
    const float* out_b     = (const float*)d_in[18];
    const float* gw1       = (const float*)d_in[19];
    const float* gb1       = (const float*)d_in[20];
    const float* gw2       = (const float*)d_in[21];
    const float* gb2       = (const float*)d_in[22];
    const float* cw1       = (const float*)d_in[23];
    const float* cb1       = (const float*)d_in[24];
    const float* cg        = (const float*)d_in[25];
    const float* cbeta     = (const float*)d_in[26];
    const float* cw2       = (const float*)d_in[27];
    const float* cb2       = (const float*)d_in[28];

    float* out = (float*)d_out;                 // [B*6 logits | B*3 gate]
    float* logits_out = out;
    float* gate_out   = out + (size_t)BATCH * 6;

    __half *rgb_h, *pose_h, *flow_h, *proj_h, *qkv_h, *ctx_h, *att_h, *gh_h, *fused_h;
    __half *rgbw_h, *posew_h, *floww_h, *inw_h, *outw_h, *gw1_h, *cw1_h;
    float *chid;
    cudaGetSymbolAddress((void**)&rgb_h,   g_rgb_h);
    cudaGetSymbolAddress((void**)&pose_h,  g_pose_h);
    cudaGetSymbolAddress((void**)&flow_h,  g_flow_h);
    cudaGetSymbolAddress((void**)&proj_h,  g_proj_h);
    cudaGetSymbolAddress((void**)&qkv_h,   g_qkv_h);
    cudaGetSymbolAddress((void**)&ctx_h,   g_ctx_h);
    cudaGetSymbolAddress((void**)&att_h,   g_att_h);
    cudaGetSymbolAddress((void**)&gh_h,    g_gh_h);
    cudaGetSymbolAddress((void**)&fused_h, g_fused_h);
    cudaGetSymbolAddress((void**)&rgbw_h,  g_rgbw_h);
    cudaGetSymbolAddress((void**)&posew_h, g_posew_h);
    cudaGetSymbolAddress((void**)&floww_h, g_floww_h);
    cudaGetSymbolAddress((void**)&inw_h,   g_inw_h);
    cudaGetSymbolAddress((void**)&outw_h,  g_outw_h);
    cudaGetSymbolAddress((void**)&gw1_h,   g_gw1_h);
    cudaGetSymbolAddress((void**)&cw1_h,   g_cw1_h);
    cudaGetSymbolAddress((void**)&chid, g_chid);

    cudaFuncSetAttribute((const void*)gemm_h<0, __half>,
        cudaFuncAttributeMaxDynamicSharedMemorySize, H_SMEM);
    cudaFuncSetAttribute((const void*)gemm_h<1, __half>,
        cudaFuncAttributeMaxDynamicSharedMemorySize, H_SMEM);
    cudaFuncSetAttribute((const void*)gemm_h<0, float>,
        cudaFuncAttributeMaxDynamicSharedMemorySize, H_SMEM);

    // 0) one fused fp32 -> fp16 convert (inputs + GEMM weights)
    {
        CvtArgs ca;
        ca.src[0] = rgb;    ca.dst[0] = rgb_h;
        ca.src[1] = pose;   ca.dst[1] = pose_h;
        ca.src[2] = flow;   ca.dst[2] = flow_h;
        ca.src[3] = rgb_w;  ca.dst[3] = rgbw_h;
        ca.src[4] = pose_w; ca.dst[4] = posew_h;
        ca.src[5] = flow_w; ca.dst[5] = floww_h;
        ca.src[6] = in_w;   ca.dst[6] = inw_h;
        ca.src[7] = out_w;  ca.dst[7] = outw_h;
        ca.src[8] = gw1;    ca.dst[8] = gw1_h;
        ca.src[9] = cw1;    ca.dst[9] = cw1_h;
        f2h_all<<<(unsigned)((CVT_TOTAL8 + 255) / 256), 256>>>(ca);
    }

    // 1) per-modality projections -> stacked/concat fp16 buffer (B,3,512)
    gemm_h<0, __half><<<dim3(4, 128), 256, H_SMEM>>>(rgb_h,  rgbw_h,  rgb_b,  proj_h + 0,    768,  1536);
    gemm_h<0, __half><<<dim3(4, 128), 256, H_SMEM>>>(pose_h, posew_h, pose_b, proj_h + 512,  640,  1536);
    gemm_h<0, __half><<<dim3(4, 128), 256, H_SMEM>>>(flow_h, floww_h, flow_b, proj_h + 1024, 1024, 1536);
    // 2) LN + ReLU per (b, modality) row (in-place fp16)
    ln_relu3_h<<<BATCH * 3, 128>>>(proj_h, rgb_g, rgb_beta, pose_g, pose_beta,
                                   flow_g, flow_beta);
    // 3) packed QKV projection: (49152 x 512) x (1536 x 512)^T -> (49152,1536)
    gemm_h<0, __half><<<dim3(12, 384), 256, H_SMEM>>>(proj_h, inw_h, in_b, qkv_h, 512, 1536);
    // 4) 3-token 8-head attention -> fp16 ctx
    attn3_h<<<BATCH * 8 / 4, 128>>>(qkv_h, ctx_h);
    // 5) attention out-projection -> fp16 att
    gemm_h<0, __half><<<dim3(4, 384), 256, H_SMEM>>>(ctx_h, outw_h, out_b, att_h, 512, 512);
    // 6) gate MLP layer 1 (proj_h as (B,1536) concat) + ReLU -> fp16 gh
    gemm_h<1, __half><<<dim3(4, 128), 256, H_SMEM>>>(proj_h, gw1_h, gb1, gh_h, 1536, 512);
    // 7) gate logits + softmax + weighted fusion -> fp16 fused + gate out
    gate_fuse_h<<<BATCH, 128>>>(gh_h, gw2, gb2, att_h, fused_h, gate_out);
    // 8) classifier layer 1 -> fp32 chid
    gemm_h<0, float><<<dim3(2, 128), 256, H_SMEM>>>(fused_h, cw1_h, cb1, chid, 512, 256);
    // 9) LN + ReLU + 6-way head
    cls_head<<<BATCH / 4, 128>>>(chid, cg, cbeta, cw2, cb2, logits_out);
}

// round 9
// speedup vs baseline: 1.2088x; 1.0175x over previous
#include <cuda_runtime.h>
#include <cuda_fp16.h>
#include <cstdint>
#include <math.h>

// ---------------------------------------------------------------------------
// AttentionFusion on GB300 (sm_103): fp16 mma.sync (m16n8k16) GEMMs via
// ldmatrix, 128x128 CTA tile / 2 CTAs/SM, single-sync multistage pipeline.
// B=16384, E=512, H=8, HD=64, NC=6.
// ---------------------------------------------------------------------------

#define BATCH 16384

// fp16 scratch
__device__ __half g_rgb_h [BATCH * 768];
__device__ __half g_pose_h[BATCH * 640];
__device__ __half g_flow_h[BATCH * 1024];
__device__ __half g_proj_h[BATCH * 1536];   // (B,3,512), post-LN in-place
__device__ __half g_qkv_h [BATCH * 4608];   // (B*3, 1536) rows
__device__ __half g_ctx_h [BATCH * 1536];
__device__ __half g_att_h [BATCH * 1536];
__device__ __half g_gh_h  [BATCH * 512];
__device__ __half g_fused_h[BATCH * 512];
// fp16 weights
__device__ __half g_rgbw_h [512 * 768];
__device__ __half g_posew_h[512 * 640];
__device__ __half g_floww_h[512 * 1024];
__device__ __half g_inw_h  [1536 * 512];
__device__ __half g_outw_h [512 * 512];
__device__ __half g_gw1_h  [512 * 1536];
__device__ __half g_cw1_h  [256 * 512];
// fp32 scratch
__device__ float g_chid[BATCH * 256];

__device__ __forceinline__ uint32_t smem_u32(const void* p) {
    uint32_t a;
    asm("{ .reg .u64 t; cvta.to.shared.u64 t, %1; cvt.u32.u64 %0, t; }"
        : "=r"(a) : "l"(p));
    return a;
}

// ---------------------------------------------------------------------------
// single fused fp32->fp16 convert over all inputs+weights
// ---------------------------------------------------------------------------
struct CvtArgs {
    const float* src[10];
    __half* dst[10];
};
__device__ __constant__ const long CVT_END[10] = {
    12582912,              // rgb     16384*768
    23068672,              // pose    +16384*640
    39845888,              // flow    +16384*1024
    40239104,              // rgbw    +512*768
    40566784,              // posew   +512*640
    41091072,              // floww   +512*1024
    41877504,              // inw     +1536*512
    42139648,              // outw    +512*512
    42926080,              // gw1     +512*1536
    43057152               // cw1     +256*512
};
constexpr long CVT_TOTAL8 = 43057152 / 8;

__global__ void __launch_bounds__(256) f2h_all(CvtArgs args)
{
    long v = (long)blockIdx.x * 256 + threadIdx.x;
    if (v >= CVT_TOTAL8) return;
    long i = v * 8;
    int s = 0;
#pragma unroll
    for (int k = 0; k < 10; k++)
        if (i >= CVT_END[k]) s = k + 1;
    long base = (s == 0) ? 0 : CVT_END[s - 1];
    long off = i - base;
    const float* in = args.src[s] + off;
    __half* out = args.dst[s] + off;
    float4 v0 = *reinterpret_cast<const float4*>(in);
    float4 v1 = *reinterpret_cast<const float4*>(in + 4);
    union { uint4 u; __half2 h[4]; } pk;
    pk.h[0] = __floats2half2_rn(v0.x, v0.y);
    pk.h[1] = __floats2half2_rn(v0.z, v0.w);
    pk.h[2] = __floats2half2_rn(v1.x, v1.y);
    pk.h[3] = __floats2half2_rn(v1.z, v1.w);
    *reinterpret_cast<uint4*>(out) = pk.u;
}

// ---------------------------------------------------------------------------
// fp16 tensor-core GEMM: C[M,N] = A[M,K] * W[N,K]^T + bias (torch Linear)
// BM=BN=128, BK=64 halves, 256 threads = 8 warps (4m x 2n), warp tile 32x64.
// 3-stage cp.async pipeline with single __syncthreads per chunk and
// (stages-1)-ahead load issue, SW128 swizzle, ldmatrix.x4, mma.m16n8k16,
// 2 CTAs/SM.  Requires M%128==0, N%128==0, K%64==0, K>=192.
// ---------------------------------------------------------------------------
constexpr int H_STAGEB = 32768;               // bytes per stage (A 16K + B 16K)
constexpr int H_SMEM   = 3 * H_STAGEB;        // 98304

__device__ __forceinline__ void storePair(float v0, float v1, __half* p) {
    *reinterpret_cast<__half2*>(p) = __floats2half2_rn(v0, v1);
}
__device__ __forceinline__ void storePair(float v0, float v1, float* p) {
    *reinterpret_cast<float2*>(p) = make_float2(v0, v1);
}

template<int RELU, typename OT>
__global__ void __launch_bounds__(256, 2) gemm_h(
    const __half* __restrict__ A, const __half* __restrict__ W,
    const float* __restrict__ bias, OT* __restrict__ C,
    int K, int ldc)
{
    extern __shared__ __align__(16) char smem[];
    const uint32_t sb = smem_u32(smem);
    const int tid = threadIdx.x;
    const int wid = tid >> 5, lane = tid & 31;
    const int q  = lane >> 2, kr = lane & 3;
    const int wm = wid & 3,  wn = wid >> 2;
    const int bm = blockIdx.y * 128, bn = blockIdx.x * 128;

    // cp.async: thread covers 64B (4 x 16B segs) of one 128B row, A and B
    const int lrow = tid >> 1;
    const int hoff = (tid & 1) * 32;               // halves
    const __half* Arow = A + (size_t)(bm + lrow) * K + hoff;
    const __half* Wrow = W + (size_t)(bn + lrow) * K + hoff;
    uint32_t dstA[4];
    {
        const uint32_t rowb = (uint32_t)lrow * 128;
        const uint32_t m = (lrow & 7) << 4;
#pragma unroll
        for (int i = 0; i < 4; i++) {
            const uint32_t seg = (tid & 1) * 4 + i;
            dstA[i] = sb + rowb + ((seg * 16) ^ m);
        }
    }

#define LOAD_CHUNK(kc_) do {                                                  \
        const uint32_t st_ = ((kc_) % 3) * H_STAGEB;                          \
        const __half* ap_ = Arow + (size_t)(kc_) * 64;                        \
        const __half* wp_ = Wrow + (size_t)(kc_) * 64;                        \
        _Pragma("unroll")                                                     \
        for (int i = 0; i < 4; i++)                                           \
            asm volatile("cp.async.cg.shared.global [%0], [%1], 16;"          \
                :: "r"(dstA[i] + st_), "l"(ap_ + i * 8) : "memory");          \
        _Pragma("unroll")                                                     \
        for (int i = 0; i < 4; i++)                                           \
            asm volatile("cp.async.cg.shared.global [%0], [%1], 16;"          \
                :: "r"(dstA[i] + st_ + 16384), "l"(wp_ + i * 8) : "memory");  \
        asm volatile("cp.async.commit_group;" ::: "memory");                  \
    } while (0)

    const int KC = K >> 6;
    // prologue: (stages-1) chunks in flight
    LOAD_CHUNK(0); LOAD_CHUNK(1);

    // ldmatrix address components (per thread)
    uint32_t rowbA[2], mAr[2], rowbB[4], mBr[4];
    const uint32_t colA0 = (lane >> 4) * 16;             // bytes
    const uint32_t colB0 = ((lane >> 3) & 1) * 16;       // bytes
#pragma unroll
    for (int t = 0; t < 2; t++) {
        const uint32_t r = wm * 32 + t * 16 + (lane & 15);
        rowbA[t] = r * 128; mAr[t] = (r & 7) << 4;
    }
#pragma unroll
    for (int jj = 0; jj < 4; jj++) {
        const uint32_t r = wn * 64 + jj * 16 + (lane & 7) + ((lane >> 4) & 1) * 8;
        rowbB[jj] = r * 128; mBr[jj] = (r & 7) << 4;
    }

    float c[2][8][4];
#pragma unroll
    for (int t = 0; t < 2; t++)
#pragma unroll
        for (int j = 0; j < 8; j++)
#pragma unroll
            for (int r = 0; r < 4; r++) c[t][j][r] = 0.f;

    for (int kc = 0; kc < KC; kc++) {
        // chunk kc resident when <=1 newer groups outstanding
        asm volatile("cp.async.wait_group 1;" ::: "memory");
        __syncthreads();
        // issue next loads BEFORE compute: stage (kc+2)%3 was consumed at
        // iteration kc-1; the barrier above proves all warps left it.
        const int kn = kc + 2;
        if (kn < KC) { LOAD_CHUNK(kn); }
        else asm volatile("cp.async.commit_group;" ::: "memory");

        const uint32_t As = sb + (kc % 3) * H_STAGEB;
        const uint32_t Bs = As + 16384;
#pragma unroll
        for (int ks = 0; ks < 4; ks++) {
            uint32_t a[2][4], b[4][4];
#pragma unroll
            for (int t = 0; t < 2; t++) {
                const uint32_t ad = As + rowbA[t] + ((colA0 + ks * 32) ^ mAr[t]);
                asm volatile(
                    "ldmatrix.sync.aligned.m8n8.x4.shared.b16 {%0,%1,%2,%3}, [%4];"
                    : "=r"(a[t][0]), "=r"(a[t][1]), "=r"(a[t][2]), "=r"(a[t][3])
                    : "r"(ad));
            }
#pragma unroll
            for (int jj = 0; jj < 4; jj++) {
                const uint32_t bd = Bs + rowbB[jj] + ((colB0 + ks * 32) ^ mBr[jj]);
                asm volatile(
                    "ldmatrix.sync.aligned.m8n8.x4.shared.b16 {%0,%1,%2,%3}, [%4];"
                    : "=r"(b[jj][0]), "=r"(b[jj][1]), "=r"(b[jj][2]), "=r"(b[jj][3])
                    : "r"(bd));
            }
#pragma unroll
            for (int t = 0; t < 2; t++)
#pragma unroll
                for (int j = 0; j < 8; j++) {
                    const int jj = j >> 1, lo = (j & 1) * 2;
                    asm volatile(
                        "mma.sync.aligned.m16n8k16.row.col.f32.f16.f16.f32 "
                        "{%0,%1,%2,%3}, {%4,%5,%6,%7}, {%8,%9}, {%0,%1,%2,%3};"
                        : "+f"(c[t][j][0]), "+f"(c[t][j][1]),
                          "+f"(c[t][j][2]), "+f"(c[t][j][3])
                        : "r"(a[t][0]), "r"(a[t][1]), "r"(a[t][2]), "r"(a[t][3]),
                          "r"(b[jj][lo]), "r"(b[jj][lo + 1]));
                }
        }
    }
#undef LOAD_CHUNK

    // epilogue: bias (+ReLU)
#pragma unroll
    for (int t = 0; t < 2; t++) {
        const int r0 = bm + wm * 32 + t * 16 + q;
#pragma unroll
        for (int j = 0; j < 8; j++) {
            const int col = bn + wn * 64 + j * 8 + (kr << 1);
            const float b0 = bias[col], b1 = bias[col + 1];
            float v00 = c[t][j][0] + b0, v01 = c[t][j][1] + b1;
            float v10 = c[t][j][2] + b0, v11 = c[t][j][3] + b1;
            if (RELU) {
                v00 = fmaxf(v00, 0.f); v01 = fmaxf(v01, 0.f);
                v10 = fmaxf(v10, 0.f); v11 = fmaxf(v11, 0.f);
            }
            storePair(v00, v01, C + (size_t)r0 * ldc + col);
            storePair(v10, v11, C + (size_t)(r0 + 8) * ldc + col);
        }
    }
}

// ---------------------------------------------------------------------------
// elementwise / small kernels
// ---------------------------------------------------------------------------
__device__ __forceinline__ float warpSum(float v) {
#pragma unroll
    for (int o = 16; o > 0; o >>= 1) v += __shfl_xor_sync(0xffffffffu, v, o);
    return v;
}

__device__ __forceinline__ float blockSum128(float v, float* sred) {
    int lane = threadIdx.x & 31, w = threadIdx.x >> 5;
    v = warpSum(v);
    __syncthreads();
    if (lane == 0) sred[w] = v;
    __syncthreads();
    return sred[0] + sred[1] + sred[2] + sred[3];
}

// in-place LN+ReLU on fp16 rows of 512; modality = row % 3
__global__ void __launch_bounds__(128) ln_relu3_h(
    __half* __restrict__ x,
    const float* __restrict__ g0, const float* __restrict__ be0,
    const float* __restrict__ g1, const float* __restrict__ be1,
    const float* __restrict__ g2, const float* __restrict__ be2)
{
    __shared__ float sred[4];
    int row = blockIdx.x;
    int s = row % 3;
    const float* g  = (s == 0) ? g0 : (s == 1) ? g1 : g2;
    const float* be = (s == 0) ? be0 : (s == 1) ? be1 : be2;
    __half* xr = x + (size_t)row * 512;
    int t = threadIdx.x;
    union { uint2 u; __half2 h[2]; } pk;
    pk.u = *reinterpret_cast<const uint2*>(xr + 4 * t);
    float2 f0 = __half22float2(pk.h[0]), f1 = __half22float2(pk.h[1]);
    float sum = blockSum128(f0.x + f0.y + f1.x + f1.y, sred);
    float mean = sum * (1.f / 512.f);
    float dx = f0.x - mean, dy = f0.y - mean, dz = f1.x - mean, dw = f1.y - mean;
    float ss = blockSum128(dx * dx + dy * dy + dz * dz + dw * dw, sred);
    float rstd = rsqrtf(ss * (1.f / 512.f) + 1e-5f);
    float4 gv = reinterpret_cast<const float4*>(g)[t];
    float4 bv = reinterpret_cast<const float4*>(be)[t];
    float ox = fmaxf(dx * rstd * gv.x + bv.x, 0.f);
    float oy = fmaxf(dy * rstd * gv.y + bv.y, 0.f);
    float oz = fmaxf(dz * rstd * gv.z + bv.z, 0.f);
    float ow = fmaxf(dw * rstd * gv.w + bv.w, 0.f);
    pk.h[0] = __floats2half2_rn(ox, oy);
    pk.h[1] = __floats2half2_rn(oz, ow);
    *reinterpret_cast<uint2*>(xr + 4 * t) = pk.u;
}

// 3-token, 8-head attention on fp16 qkv; one warp per (sample, head)
__global__ void __launch_bounds__(128) attn3_h(
    const __half* __restrict__ qkv, __half* __restrict__ ctx)
{
    int warp = blockIdx.x * 4 + (threadIdx.x >> 5);
    int lane = threadIdx.x & 31;
    int b = warp >> 3, h = warp & 7;
    const __half* base = qkv + (size_t)b * 4608 + h * 64 + 2 * lane;
    float2 q[3], k[3], v[3];
#pragma unroll
    for (int t = 0; t < 3; t++) {
        q[t] = __half22float2(*reinterpret_cast<const __half2*>(base + t * 1536));
        k[t] = __half22float2(*reinterpret_cast<const __half2*>(base + t * 1536 + 512));
        v[t] = __half22float2(*reinterpret_cast<const __half2*>(base + t * 1536 + 1024));
    }
    float a[3][3];
#pragma unroll
    for (int i = 0; i < 3; i++)
#pragma unroll
        for (int j = 0; j < 3; j++) {
            float p = q[i].x * k[j].x + q[i].y * k[j].y;
            a[i][j] = warpSum(p) * 0.125f;
        }
#pragma unroll
    for (int i = 0; i < 3; i++) {
        float m = fmaxf(a[i][0], fmaxf(a[i][1], a[i][2]));
        float e0 = expf(a[i][0] - m), e1 = expf(a[i][1] - m), e2 = expf(a[i][2] - m);
        float inv = 1.f / (e0 + e1 + e2);
        a[i][0] = e0 * inv; a[i][1] = e1 * inv; a[i][2] = e2 * inv;
    }
#pragma unroll
    for (int i = 0; i < 3; i++) {
        float ox = a[i][0] * v[0].x + a[i][1] * v[1].x + a[i][2] * v[2].x;
        float oy = a[i][0] * v[0].y + a[i][1] * v[1].y + a[i][2] * v[2].y;
        *reinterpret_cast<__half2*>(ctx + (size_t)(b * 3 + i) * 512 + h * 64 + 2 * lane)
            = __floats2half2_rn(ox, oy);
    }
}

// gate logits + softmax + weighted fuse (fp16 gh/att) -> fp16 fused + f32 gate
__global__ void __launch_bounds__(128) gate_fuse_h(
    const __half* __restrict__ gh, const float* __restrict__ gw2,
    const float* __restrict__ gb2, const __half* __restrict__ att,
    __half* __restrict__ fused, float* __restrict__ gate_out)
{
    __shared__ float sred[4];
    int b = blockIdx.x, t = threadIdx.x;
    union { uint2 u; __half2 h[2]; } hv;
    hv.u = *reinterpret_cast<const uint2*>(gh + (size_t)b * 512 + 4 * t);
    float2 h0 = __half22float2(hv.h[0]), h1 = __half22float2(hv.h[1]);
    float l[3];
#pragma unroll
    for (int s = 0; s < 3; s++) {
        float4 w = reinterpret_cast<const float4*>(gw2 + s * 512)[t];
        l[s] = blockSum128(h0.x * w.x + h0.y * w.y + h1.x * w.z + h1.y * w.w, sred)
             + gb2[s];
    }
    float m = fmaxf(l[0], fmaxf(l[1], l[2]));
    float e0 = expf(l[0] - m), e1 = expf(l[1] - m), e2 = expf(l[2] - m);
    float inv = 1.f / (e0 + e1 + e2);
    float w0 = e0 * inv, w1 = e1 * inv, w2 = e2 * inv;
    if (t == 0) {
        gate_out[b * 3 + 0] = w0;
        gate_out[b * 3 + 1] = w1;
        gate_out[b * 3 + 2] = w2;
    }
    const __half* ab = att + (size_t)b * 1536 + 4 * t;
    union { uint2 u; __half2 h[2]; } x0, x1, x2;
    x0.u = *reinterpret_cast<const uint2*>(ab);
    x1.u = *reinterpret_cast<const uint2*>(ab + 512);
    x2.u = *reinterpret_cast<const uint2*>(ab + 1024);
    float2 a0 = __half22float2(x0.h[0]), b0f = __half22float2(x0.h[1]);
    float2 a1 = __half22float2(x1.h[0]), b1f = __half22float2(x1.h[1]);
    float2 a2 = __half22float2(x2.h[0]), b2f = __half22float2(x2.h[1]);
    union { uint2 u; __half2 h[2]; } pk;
    pk.h[0] = __floats2half2_rn(w0 * a0.x + w1 * a1.x + w2 * a2.x,
                                w0 * a0.y + w1 * a1.y + w2 * a2.y);
    pk.h[1] = __floats2half2_rn(w0 * b0f.x + w1 * b1f.x + w2 * b2f.x,
                                w0 * b0f.y + w1 * b1f.y + w2 * b2f.y);
    *reinterpret_cast<uint2*>(fused + (size_t)b * 512 + 4 * t) = pk.u;
}

// classifier head: LN(256) + ReLU + 6-way linear; one warp per sample
__global__ void __launch_bounds__(128) cls_head(
    const float* __restrict__ chid, const float* __restrict__ cg,
    const float* __restrict__ cbeta, const float* __restrict__ cw2,
    const float* __restrict__ cb2, float* __restrict__ logits)
{
    int b = blockIdx.x * 4 + (threadIdx.x >> 5);
    int lane = threadIdx.x & 31;
    const float* hr = chid + (size_t)b * 256;
    float4 h0 = reinterpret_cast<const float4*>(hr)[lane];
    float4 h1 = reinterpret_cast<const float4*>(hr)[lane + 32];
    float sum = warpSum(h0.x + h0.y + h0.z + h0.w + h1.x + h1.y + h1.z + h1.w);
    float mean = sum * (1.f / 256.f);
    h0.x -= mean; h0.y -= mean; h0.z -= mean; h0.w -= mean;
    h1.x -= mean; h1.y -= mean; h1.z -= mean; h1.w -= mean;
    float ss = warpSum(h0.x * h0.x + h0.y * h0.y + h0.z * h0.z + h0.w * h0.w
                     + h1.x * h1.x + h1.y * h1.y + h1.z * h1.z + h1.w * h1.w);
    float rstd = rsqrtf(ss * (1.f / 256.f) + 1e-5f);
    float4 cg0 = reinterpret_cast<const float4*>(cg)[lane];
    float4 cg1 = reinterpret_cast<const float4*>(cg)[lane + 32];
    float4 cb0 = reinterpret_cast<const float4*>(cbeta)[lane];
    float4 cb1 = reinterpret_cast<const float4*>(cbeta)[lane + 32];
    h0.x = fmaxf(h0.x * rstd * cg0.x + cb0.x, 0.f);
    h0.y = fmaxf(h0.y * rstd * cg0.y + cb0.y, 0.f);
    h0.z = fmaxf(h0.z * rstd * cg0.z + cb0.z, 0.f);
    h0.w = fmaxf(h0.w * rstd * cg0.w + cb0.w, 0.f);
    h1.x = fmaxf(h1.x * rstd * cg1.x + cb1.x, 0.f);
    h1.y = fmaxf(h1.y * rstd * cg1.y + cb1.y, 0.f);
    h1.z = fmaxf(h1.z * rstd * cg1.z + cb1.z, 0.f);
    h1.w = fmaxf(h1.w * rstd * cg1.w + cb1.w, 0.f);
#pragma unroll
    for (int c = 0; c < 6; c++) {
        const float4* wr = reinterpret_cast<const float4*>(cw2 + c * 256);
        float4 w0 = wr[lane], w1 = wr[lane + 32];
        float p = h0.x * w0.x + h0.y * w0.y + h0.z * w0.z + h0.w * w0.w
                + h1.x * w1.x + h1.y * w1.y + h1.z * w1.z + h1.w * w1.w;
        p = warpSum(p);
        if (lane == 0) logits[(size_t)b * 6 + c] = p + cb2[c];
    }
}

// ---------------------------------------------------------------------------
extern "C" void kernel_launch(void* const* d_in, const int* in_sizes, int n_in,
                              void* d_out, int out_size)
{
    const float* rgb       = (const float*)d_in[0];
    const float* pose      = (const float*)d_in[1];
    const float* flow      = (const float*)d_in[2];
    const float* rgb_w     = (const float*)d_in[3];
    const float* rgb_b     = (const float*)d_in[4];
    const float* rgb_g     = (const float*)d_in[5];
    const float* rgb_beta  = (const float*)d_in[6];
    const float* pose_w    = (const float*)d_in[7];
    const float* pose_b    = (const float*)d_in[8];
    const float* pose_g    = (const float*)d_in[9];
    const float* pose_beta = (const float*)d_in[10];
    const float* flow_w    = (const float*)d_in[11];
    const float* flow_b    = (const float*)d_in[12];
    const float* flow_g    = (const float*)d_in[13];
    const float* flow_beta = (const float*)d_in[14];
    const float* in_w      = (const float*)d_in[15];
    const float* in_b      = (const float*)d_in[16];
    const float* out_w     = (const float*)d_in[17];
    const float* out_b     = (const float*)d_in[18];
    const float* gw1       = (const float*)d_in[19];
    const float* gb1       = (const float*)d_in[20];
    const float* gw2       = (const float*)d_in[21];
    const float* gb2       = (const float*)d_in[22];
    const float* cw1       = (const float*)d_in[23];
    const float* cb1       = (const float*)d_in[24];
    const float* cg        = (const float*)d_in[25];
    const float* cbeta     = (const float*)d_in[26];
    const float* cw2       = (const float*)d_in[27];
    const float* cb2       = (const float*)d_in[28];

    float* out = (float*)d_out;                 // [B*6 logits | B*3 gate]
    float* logits_out = out;
    float* gate_out   = out + (size_t)BATCH * 6;

    __half *rgb_h, *pose_h, *flow_h, *proj_h, *qkv_h, *ctx_h, *att_h, *gh_h, *fused_h;
    __half *rgbw_h, *posew_h, *floww_h, *inw_h, *outw_h, *gw1_h, *cw1_h;
    float *chid;
    cudaGetSymbolAddress((void**)&rgb_h,   g_rgb_h);
    cudaGetSymbolAddress((void**)&pose_h,  g_pose_h);
    cudaGetSymbolAddress((void**)&flow_h,  g_flow_h);
    cudaGetSymbolAddress((void**)&proj_h,  g_proj_h);
    cudaGetSymbolAddress((void**)&qkv_h,   g_qkv_h);
    cudaGetSymbolAddress((void**)&ctx_h,   g_ctx_h);
    cudaGetSymbolAddress((void**)&att_h,   g_att_h);
    cudaGetSymbolAddress((void**)&gh_h,    g_gh_h);
    cudaGetSymbolAddress((void**)&fused_h, g_fused_h);
    cudaGetSymbolAddress((void**)&rgbw_h,  g_rgbw_h);
    cudaGetSymbolAddress((void**)&posew_h, g_posew_h);
    cudaGetSymbolAddress((void**)&floww_h, g_floww_h);
    cudaGetSymbolAddress((void**)&inw_h,   g_inw_h);
    cudaGetSymbolAddress((void**)&outw_h,  g_outw_h);
    cudaGetSymbolAddress((void**)&gw1_h,   g_gw1_h);
    cudaGetSymbolAddress((void**)&cw1_h,   g_cw1_h);
    cudaGetSymbolAddress((void**)&chid, g_chid);

    cudaFuncSetAttribute((const void*)gemm_h<0, __half>,
        cudaFuncAttributeMaxDynamicSharedMemorySize, H_SMEM);
    cudaFuncSetAttribute((const void*)gemm_h<1, __half>,
        cudaFuncAttributeMaxDynamicSharedMemorySize, H_SMEM);
    cudaFuncSetAttribute((const void*)gemm_h<0, float>,
        cudaFuncAttributeMaxDynamicSharedMemorySize, H_SMEM);

    // 0) one fused fp32 -> fp16 convert (inputs + GEMM weights)
    {
        CvtArgs ca;
        ca.src[0] = rgb;    ca.dst[0] = rgb_h;
        ca.src[1] = pose;   ca.dst[1] = pose_h;
        ca.src[2] = flow;   ca.dst[2] = flow_h;
        ca.src[3] = rgb_w;  ca.dst[3] = rgbw_h;
        ca.src[4] = pose_w; ca.dst[4] = posew_h;
        ca.src[5] = flow_w; ca.dst[5] = floww_h;
        ca.src[6] = in_w;   ca.dst[6] = inw_h;
        ca.src[7] = out_w;  ca.dst[7] = outw_h;
        ca.src[8] = gw1;    ca.dst[8] = gw1_h;
        ca.src[9] = cw1;    ca.dst[9] = cw1_h;
        f2h_all<<<(unsigned)((CVT_TOTAL8 + 255) / 256), 256>>>(ca);
    }

    // 1) per-modality projections -> stacked/concat fp16 buffer (B,3,512)
    gemm_h<0, __half><<<dim3(4, 128), 256, H_SMEM>>>(rgb_h,  rgbw_h,  rgb_b,  proj_h + 0,    768,  1536);
    gemm_h<0, __half><<<dim3(4, 128), 256, H_SMEM>>>(pose_h, posew_h, pose_b, proj_h + 512,  640,  1536);
    gemm_h<0, __half><<<dim3(4, 128), 256, H_SMEM>>>(flow_h, floww_h, flow_b, proj_h + 1024, 1024, 1536);
    // 2) LN + ReLU per (b, modality) row (in-place fp16)
    ln_relu3_h<<<BATCH * 3, 128>>>(proj_h, rgb_g, rgb_beta, pose_g, pose_beta,
                                   flow_g, flow_beta);
    // 3) packed QKV projection: (49152 x 512) x (1536 x 512)^T -> (49152,1536)
    gemm_h<0, __half><<<dim3(12, 384), 256, H_SMEM>>>(proj_h, inw_h, in_b, qkv_h, 512, 1536);
    // 4) 3-token 8-head attention -> fp16 ctx
    attn3_h<<<BATCH * 8 / 4, 128>>>(qkv_h, ctx_h);
    // 5) attention out-projection -> fp16 att
    gemm_h<0, __half><<<dim3(4, 384), 256, H_SMEM>>>(ctx_h, outw_h, out_b, att_h, 512, 512);
    // 6) gate MLP layer 1 (proj_h as (B,1536) concat) + ReLU -> fp16 gh
    gemm_h<1, __half><<<dim3(4, 128), 256, H_SMEM>>>(proj_h, gw1_h, gb1, gh_h, 1536, 512);
    // 7) gate logits + softmax + weighted fusion -> fp16 fused + gate out
    gate_fuse_h<<<BATCH, 128>>>(gh_h, gw2, gb2, att_h, fused_h, gate_out);
    // 8) classifier layer 1 -> fp32 chid
    gemm_h<0, float><<<dim3(2, 128), 256, H_SMEM>>>(fused_h, cw1_h, cb1, chid, 512, 256);
    // 9) LN + ReLU + 6-way head
    cls_head<<<BATCH / 4, 128>>>(chid, cg, cbeta, cw2, cb2, logits_out);
}

// round 13
// speedup vs baseline: 1.2759x; 1.0555x over previous
#include <cuda_runtime.h>
#include <cuda_fp16.h>
#include <cstdint>
#include <math.h>

// ---------------------------------------------------------------------------
// AttentionFusion on GB300 (sm_103): fp16 mma.sync (m16n8k16) GEMMs via
// ldmatrix, 128x128 CTA tile / 2 CTAs/SM, single-sync multistage pipeline,
// batched-GEMM megakernel to kill wave-quantization waste.
// B=16384, E=512, H=8, HD=64, NC=6.
// ---------------------------------------------------------------------------

#define BATCH 16384

// fp16 scratch
__device__ __half g_rgb_h [BATCH * 768];
__device__ __half g_pose_h[BATCH * 640];
__device__ __half g_flow_h[BATCH * 1024];
__device__ __half g_proj_h[BATCH * 1536];   // (B,3,512), post-LN in-place
__device__ __half g_qkv_h [BATCH * 4608];   // (B*3, 1536) rows
__device__ __half g_ctx_h [BATCH * 1536];
__device__ __half g_att_h [BATCH * 1536];
__device__ __half g_gh_h  [BATCH * 512];
__device__ __half g_fused_h[BATCH * 512];
// fp16 weights
__device__ __half g_rgbw_h [512 * 768];
__device__ __half g_posew_h[512 * 640];
__device__ __half g_floww_h[512 * 1024];
__device__ __half g_inw_h  [1536 * 512];
__device__ __half g_outw_h [512 * 512];
__device__ __half g_gw1_h  [512 * 1536];
__device__ __half g_cw1_h  [256 * 512];
// fp32 scratch
__device__ float g_chid[BATCH * 256];

__device__ __forceinline__ uint32_t smem_u32(const void* p) {
    uint32_t a;
    asm("{ .reg .u64 t; cvta.to.shared.u64 t, %1; cvt.u32.u64 %0, t; }"
        : "=r"(a) : "l"(p));
    return a;
}

// ---------------------------------------------------------------------------
// single fused fp32->fp16 convert over all inputs+weights
// ---------------------------------------------------------------------------
struct CvtArgs {
    const float* src[10];
    __half* dst[10];
};
__device__ __constant__ const long CVT_END[10] = {
    12582912,              // rgb     16384*768
    23068672,              // pose    +16384*640
    39845888,              // flow    +16384*1024
    40239104,              // rgbw    +512*768
    40566784,              // posew   +512*640
    41091072,              // floww   +512*1024
    41877504,              // inw     +1536*512
    42139648,              // outw    +512*512
    42926080,              // gw1     +512*1536
    43057152               // cw1     +256*512
};
constexpr long CVT_TOTAL8 = 43057152 / 8;

__global__ void __launch_bounds__(256) f2h_all(CvtArgs args)
{
    long v = (long)blockIdx.x * 256 + threadIdx.x;
    if (v >= CVT_TOTAL8) return;
    long i = v * 8;
    int s = 0;
#pragma unroll
    for (int k = 0; k < 10; k++)
        if (i >= CVT_END[k]) s = k + 1;
    long base = (s == 0) ? 0 : CVT_END[s - 1];
    long off = i - base;
    const float* in = args.src[s] + off;
    __half* out = args.dst[s] + off;
    float4 v0 = *reinterpret_cast<const float4*>(in);
    float4 v1 = *reinterpret_cast<const float4*>(in + 4);
    union { uint4 u; __half2 h[4]; } pk;
    pk.h[0] = __floats2half2_rn(v0.x, v0.y);
    pk.h[1] = __floats2half2_rn(v0.z, v0.w);
    pk.h[2] = __floats2half2_rn(v1.x, v1.y);
    pk.h[3] = __floats2half2_rn(v1.z, v1.w);
    *reinterpret_cast<uint4*>(out) = pk.u;
}

// ---------------------------------------------------------------------------
// shared GEMM core: C[M,N] = A[M,K] * W[N,K]^T + bias (torch Linear layout)
// BM=BN=128, BK=64 halves, 256 threads = 8 warps (4m x 2n), warp tile 32x64.
// 3-stage cp.async pipeline, single __syncthreads per chunk, SW128 swizzle,
// ldmatrix.x4, mma.m16n8k16, 2 CTAs/SM.
// ---------------------------------------------------------------------------
constexpr int H_STAGEB = 32768;               // bytes per stage (A 16K + B 16K)
constexpr int H_SMEM   = 3 * H_STAGEB;        // 98304

__device__ __forceinline__ void storePair(float v0, float v1, __half* p) {
    *reinterpret_cast<__half2*>(p) = __floats2half2_rn(v0, v1);
}
__device__ __forceinline__ void storePair(float v0, float v1, float* p) {
    *reinterpret_cast<float2*>(p) = make_float2(v0, v1);
}

template<typename OT>
__device__ __forceinline__ void gemm_core(
    const __half* __restrict__ A, const __half* __restrict__ W,
    const float* __restrict__ bias, OT* __restrict__ C,
    int K, int ldc, int relu, int bm, int bn, uint32_t sb)
{
    const int tid = threadIdx.x;
    const int wid = tid >> 5, lane = tid & 31;
    const int q  = lane >> 2, kr = lane & 3;
    const int wm = wid & 3,  wn = wid >> 2;

    // cp.async: thread covers 64B (4 x 16B segs) of one 128B row, A and B
    const int lrow = tid >> 1;
    const int hoff = (tid & 1) * 32;               // halves
    const __half* Arow = A + (size_t)(bm + lrow) * K + hoff;
    const __half* Wrow = W + (size_t)(bn + lrow) * K + hoff;
    uint32_t dstA[4];
    {
        const uint32_t rowb = (uint32_t)lrow * 128;
        const uint32_t m = (lrow & 7) << 4;
#pragma unroll
        for (int i = 0; i < 4; i++) {
            const uint32_t seg = (tid & 1) * 4 + i;
            dstA[i] = sb + rowb + ((seg * 16) ^ m);
        }
    }

#define LOAD_CHUNK(kc_) do {                                                  \
        const uint32_t st_ = ((kc_) % 3) * H_STAGEB;                          \
        const __half* ap_ = Arow + (size_t)(kc_) * 64;                        \
        const __half* wp_ = Wrow + (size_t)(kc_) * 64;                        \
        _Pragma("unroll")                                                     \
        for (int i = 0; i < 4; i++)                                           \
            asm volatile("cp.async.cg.shared.global [%0], [%1], 16;"          \
                :: "r"(dstA[i] + st_), "l"(ap_ + i * 8) : "memory");          \
        _Pragma("unroll")                                                     \
        for (int i = 0; i < 4; i++)                                           \
            asm volatile("cp.async.cg.shared.global [%0], [%1], 16;"          \
                :: "r"(dstA[i] + st_ + 16384), "l"(wp_ + i * 8) : "memory");  \
        asm volatile("cp.async.commit_group;" ::: "memory");                  \
    } while (0)

    const int KC = K >> 6;
    // prologue: (stages-1) chunks in flight
    LOAD_CHUNK(0); LOAD_CHUNK(1);

    // ldmatrix address components (per thread)
    uint32_t rowbA[2], mAr[2], rowbB[4], mBr[4];
    const uint32_t colA0 = (lane >> 4) * 16;             // bytes
    const uint32_t colB0 = ((lane >> 3) & 1) * 16;       // bytes
#pragma unroll
    for (int t = 0; t < 2; t++) {
        const uint32_t r = wm * 32 + t * 16 + (lane & 15);
        rowbA[t] = r * 128; mAr[t] = (r & 7) << 4;
    }
#pragma unroll
    for (int jj = 0; jj < 4; jj++) {
        const uint32_t r = wn * 64 + jj * 16 + (lane & 7) + ((lane >> 4) & 1) * 8;
        rowbB[jj] = r * 128; mBr[jj] = (r & 7) << 4;
    }

    float c[2][8][4];
#pragma unroll
    for (int t = 0; t < 2; t++)
#pragma unroll
        for (int j = 0; j < 8; j++)
#pragma unroll
            for (int r = 0; r < 4; r++) c[t][j][r] = 0.f;

    for (int kc = 0; kc < KC; kc++) {
        // chunk kc resident when <=1 newer groups outstanding
        asm volatile("cp.async.wait_group 1;" ::: "memory");
        __syncthreads();
        // issue next loads BEFORE compute: stage (kc+2)%3 was consumed at
        // iteration kc-1; the barrier above proves all warps left it.
        const int kn = kc + 2;
        if (kn < KC) { LOAD_CHUNK(kn); }
        else asm volatile("cp.async.commit_group;" ::: "memory");

        const uint32_t As = sb + (kc % 3) * H_STAGEB;
        const uint32_t Bs = As + 16384;
#pragma unroll
        for (int ks = 0; ks < 4; ks++) {
            uint32_t a[2][4], b[4][4];
#pragma unroll
            for (int t = 0; t < 2; t++) {
                const uint32_t ad = As + rowbA[t] + ((colA0 + ks * 32) ^ mAr[t]);
                asm volatile(
                    "ldmatrix.sync.aligned.m8n8.x4.shared.b16 {%0,%1,%2,%3}, [%4];"
                    : "=r"(a[t][0]), "=r"(a[t][1]), "=r"(a[t][2]), "=r"(a[t][3])
                    : "r"(ad));
            }
#pragma unroll
            for (int jj = 0; jj < 4; jj++) {
                const uint32_t bd = Bs + rowbB[jj] + ((colB0 + ks * 32) ^ mBr[jj]);
                asm volatile(
                    "ldmatrix.sync.aligned.m8n8.x4.shared.b16 {%0,%1,%2,%3}, [%4];"
                    : "=r"(b[jj][0]), "=r"(b[jj][1]), "=r"(b[jj][2]), "=r"(b[jj][3])
                    : "r"(bd));
            }
#pragma unroll
            for (int t = 0; t < 2; t++)
#pragma unroll
                for (int j = 0; j < 8; j++) {
                    const int jj = j >> 1, lo = (j & 1) * 2;
                    asm volatile(
                        "mma.sync.aligned.m16n8k16.row.col.f32.f16.f16.f32 "
                        "{%0,%1,%2,%3}, {%4,%5,%6,%7}, {%8,%9}, {%0,%1,%2,%3};"
                        : "+f"(c[t][j][0]), "+f"(c[t][j][1]),
                          "+f"(c[t][j][2]), "+f"(c[t][j][3])
                        : "r"(a[t][0]), "r"(a[t][1]), "r"(a[t][2]), "r"(a[t][3]),
                          "r"(b[jj][lo]), "r"(b[jj][lo + 1]));
                }
        }
    }
#undef LOAD_CHUNK

    // epilogue: bias (+ReLU, uniform runtime branch)
#pragma unroll
    for (int t = 0; t < 2; t++) {
        const int r0 = bm + wm * 32 + t * 16 + q;
#pragma unroll
        for (int j = 0; j < 8; j++) {
            const int col = bn + wn * 64 + j * 8 + (kr << 1);
            const float b0 = bias[col], b1 = bias[col + 1];
            float v00 = c[t][j][0] + b0, v01 = c[t][j][1] + b1;
            float v10 = c[t][j][2] + b0, v11 = c[t][j][3] + b1;
            if (relu) {
                v00 = fmaxf(v00, 0.f); v01 = fmaxf(v01, 0.f);
                v10 = fmaxf(v10, 0.f); v11 = fmaxf(v11, 0.f);
            }
            storePair(v00, v01, C + (size_t)r0 * ldc + col);
            storePair(v10, v11, C + (size_t)(r0 + 8) * ldc + col);
        }
    }
}

// single-op GEMM wrapper (outproj half, cls1 float)
template<int RELU, typename OT>
__global__ void __launch_bounds__(256, 2) gemm_h(
    const __half* __restrict__ A, const __half* __restrict__ W,
    const float* __restrict__ bias, OT* __restrict__ C,
    int K, int ldc)
{
    extern __shared__ __align__(16) char smem[];
    gemm_core<OT>(A, W, bias, C, K, ldc, RELU,
                  blockIdx.y * 128, blockIdx.x * 128, smem_u32(smem));
}

// batched GEMM: up to 3 ops in one launch; linear blockIdx -> (op, bx, by)
struct BatchDesc {
    const __half* A[3];
    const __half* W[3];
    const float*  bias[3];
    __half*       C[3];
    int K[3], ldc[3], relu[3], gx[3], cnt[3];
    int nops;
};

__global__ void __launch_bounds__(256, 2) gemm_batch(BatchDesc d)
{
    extern __shared__ __align__(16) char smem[];
    int id = blockIdx.x;
    int op = 0;
    while (op + 1 < d.nops && id >= d.cnt[op]) { id -= d.cnt[op]; ++op; }
    const int gx = d.gx[op];
    const int bx = id % gx, by = id / gx;
    gemm_core<__half>(d.A[op], d.W[op], d.bias[op], d.C[op],
                      d.K[op], d.ldc[op], d.relu[op],
                      by * 128, bx * 128, smem_u32(smem));
}

// ---------------------------------------------------------------------------
// elementwise / small kernels
// ---------------------------------------------------------------------------
__device__ __forceinline__ float warpSum(float v) {
#pragma unroll
    for (int o = 16; o > 0; o >>= 1) v += __shfl_xor_sync(0xffffffffu, v, o);
    return v;
}

__device__ __forceinline__ float blockSum128(float v, float* sred) {
    int lane = threadIdx.x & 31, w = threadIdx.x >> 5;
    v = warpSum(v);
    __syncthreads();
    if (lane == 0) sred[w] = v;
    __syncthreads();
    return sred[0] + sred[1] + sred[2] + sred[3];
}

// in-place LN+ReLU on fp16 rows of 512; modality = row % 3
__global__ void __launch_bounds__(128) ln_relu3_h(
    __half* __restrict__ x,
    const float* __restrict__ g0, const float* __restrict__ be0,
    const float* __restrict__ g1, const float* __restrict__ be1,
    const float* __restrict__ g2, const float* __restrict__ be2)
{
    __shared__ float sred[4];
    int row = blockIdx.x;
    int s = row % 3;
    const float* g  = (s == 0) ? g0 : (s == 1) ? g1 : g2;
    const float* be = (s == 0) ? be0 : (s == 1) ? be1 : be2;
    __half* xr = x + (size_t)row * 512;
    int t = threadIdx.x;
    union { uint2 u; __half2 h[2]; } pk;
    pk.u = *reinterpret_cast<const uint2*>(xr + 4 * t);
    float2 f0 = __half22float2(pk.h[0]), f1 = __half22float2(pk.h[1]);
    float sum = blockSum128(f0.x + f0.y + f1.x + f1.y, sred);
    float mean = sum * (1.f / 512.f);
    float dx = f0.x - mean, dy = f0.y - mean, dz = f1.x - mean, dw = f1.y - mean;
    float ss = blockSum128(dx * dx + dy * dy + dz * dz + dw * dw, sred);
    float rstd = rsqrtf(ss * (1.f / 512.f) + 1e-5f);
    float4 gv = reinterpret_cast<const float4*>(g)[t];
    float4 bv = reinterpret_cast<const float4*>(be)[t];
    float ox = fmaxf(dx * rstd * gv.x + bv.x, 0.f);
    float oy = fmaxf(dy * rstd * gv.y + bv.y, 0.f);
    float oz = fmaxf(dz * rstd * gv.z + bv.z, 0.f);
    float ow = fmaxf(dw * rstd * gv.w + bv.w, 0.f);
    pk.h[0] = __floats2half2_rn(ox, oy);
    pk.h[1] = __floats2half2_rn(oz, ow);
    *reinterpret_cast<uint2*>(xr + 4 * t) = pk.u;
}

// 3-token, 8-head attention on fp16 qkv; one warp per (sample, head)
__global__ void __launch_bounds__(128) attn3_h(
    const __half* __restrict__ qkv, __half* __restrict__ ctx)
{
    int warp = blockIdx.x * 4 + (threadIdx.x >> 5);
    int lane = threadIdx.x & 31;
    int b = warp >> 3, h = warp & 7;
    const __half* base = qkv + (size_t)b * 4608 + h * 64 + 2 * lane;
    float2 q[3], k[3], v[3];
#pragma unroll
    for (int t = 0; t < 3; t++) {
        q[t] = __half22float2(*reinterpret_cast<const __half2*>(base + t * 1536));
        k[t] = __half22float2(*reinterpret_cast<const __half2*>(base + t * 1536 + 512));
        v[t] = __half22float2(*reinterpret_cast<const __half2*>(base + t * 1536 + 1024));
    }
    float a[3][3];
#pragma unroll
    for (int i = 0; i < 3; i++)
#pragma unroll
        for (int j = 0; j < 3; j++) {
            float p = q[i].x * k[j].x + q[i].y * k[j].y;
            a[i][j] = warpSum(p) * 0.125f;
        }
#pragma unroll
    for (int i = 0; i < 3; i++) {
        float m = fmaxf(a[i][0], fmaxf(a[i][1], a[i][2]));
        float e0 = expf(a[i][0] - m), e1 = expf(a[i][1] - m), e2 = expf(a[i][2] - m);
        float inv = 1.f / (e0 + e1 + e2);
        a[i][0] = e0 * inv; a[i][1] = e1 * inv; a[i][2] = e2 * inv;
    }
#pragma unroll
    for (int i = 0; i < 3; i++) {
        float ox = a[i][0] * v[0].x + a[i][1] * v[1].x + a[i][2] * v[2].x;
        float oy = a[i][0] * v[0].y + a[i][1] * v[1].y + a[i][2] * v[2].y;
        *reinterpret_cast<__half2*>(ctx + (size_t)(b * 3 + i) * 512 + h * 64 + 2 * lane)
            = __floats2half2_rn(ox, oy);
    }
}

// gate logits + softmax + weighted fuse (fp16 gh/att) -> fp16 fused + f32 gate
__global__ void __launch_bounds__(128) gate_fuse_h(
    const __half* __restrict__ gh, const float* __restrict__ gw2,
    const float* __restrict__ gb2, const __half* __restrict__ att,
    __half* __restrict__ fused, float* __restrict__ gate_out)
{
    __shared__ float sred[4];
    int b = blockIdx.x, t = threadIdx.x;
    union { uint2 u; __half2 h[2]; } hv;
    hv.u = *reinterpret_cast<const uint2*>(gh + (size_t)b * 512 + 4 * t);
    float2 h0 = __half22float2(hv.h[0]), h1 = __half22float2(hv.h[1]);
    float l[3];
#pragma unroll
    for (int s = 0; s < 3; s++) {
        float4 w = reinterpret_cast<const float4*>(gw2 + s * 512)[t];
        l[s] = blockSum128(h0.x * w.x + h0.y * w.y + h1.x * w.z + h1.y * w.w, sred)
             + gb2[s];
    }
    float m = fmaxf(l[0], fmaxf(l[1], l[2]));
    float e0 = expf(l[0] - m), e1 = expf(l[1] - m), e2 = expf(l[2] - m);
    float inv = 1.f / (e0 + e1 + e2);
    float w0 = e0 * inv, w1 = e1 * inv, w2 = e2 * inv;
    if (t == 0) {
        gate_out[b * 3 + 0] = w0;
        gate_out[b * 3 + 1] = w1;
        gate_out[b * 3 + 2] = w2;
    }
    const __half* ab = att + (size_t)b * 1536 + 4 * t;
    union { uint2 u; __half2 h[2]; } x0, x1, x2;
    x0.u = *reinterpret_cast<const uint2*>(ab);
    x1.u = *reinterpret_cast<const uint2*>(ab + 512);
    x2.u = *reinterpret_cast<const uint2*>(ab + 1024);
    float2 a0 = __half22float2(x0.h[0]), b0f = __half22float2(x0.h[1]);
    float2 a1 = __half22float2(x1.h[0]), b1f = __half22float2(x1.h[1]);
    float2 a2 = __half22float2(x2.h[0]), b2f = __half22float2(x2.h[1]);
    union { uint2 u; __half2 h[2]; } pk;
    pk.h[0] = __floats2half2_rn(w0 * a0.x + w1 * a1.x + w2 * a2.x,
                                w0 * a0.y + w1 * a1.y + w2 * a2.y);
    pk.h[1] = __floats2half2_rn(w0 * b0f.x + w1 * b1f.x + w2 * b2f.x,
                                w0 * b0f.y + w1 * b1f.y + w2 * b2f.y);
    *reinterpret_cast<uint2*>(fused + (size_t)b * 512 + 4 * t) = pk.u;
}

// classifier head: LN(256) + ReLU + 6-way linear; one warp per sample
__global__ void __launch_bounds__(128) cls_head(
    const float* __restrict__ chid, const float* __restrict__ cg,
    const float* __restrict__ cbeta, const float* __restrict__ cw2,
    const float* __restrict__ cb2, float* __restrict__ logits)
{
    int b = blockIdx.x * 4 + (threadIdx.x >> 5);
    int lane = threadIdx.x & 31;
    const float* hr = chid + (size_t)b * 256;
    float4 h0 = reinterpret_cast<const float4*>(hr)[lane];
    float4 h1 = reinterpret_cast<const float4*>(hr)[lane + 32];
    float sum = warpSum(h0.x + h0.y + h0.z + h0.w + h1.x + h1.y + h1.z + h1.w);
    float mean = sum * (1.f / 256.f);
    h0.x -= mean; h0.y -= mean; h0.z -= mean; h0.w -= mean;
    h1.x -= mean; h1.y -= mean; h1.z -= mean; h1.w -= mean;
    float ss = warpSum(h0.x * h0.x + h0.y * h0.y + h0.z * h0.z + h0.w * h0.w
                     + h1.x * h1.x + h1.y * h1.y + h1.z * h1.z + h1.w * h1.w);
    float rstd = rsqrtf(ss * (1.f / 256.f) + 1e-5f);
    float4 cg0 = reinterpret_cast<const float4*>(cg)[lane];
    float4 cg1 = reinterpret_cast<const float4*>(cg)[lane + 32];
    float4 cb0 = reinterpret_cast<const float4*>(cbeta)[lane];
    float4 cb1 = reinterpret_cast<const float4*>(cbeta)[lane + 32];
    h0.x = fmaxf(h0.x * rstd * cg0.x + cb0.x, 0.f);
    h0.y = fmaxf(h0.y * rstd * cg0.y + cb0.y, 0.f);
    h0.z = fmaxf(h0.z * rstd * cg0.z + cb0.z, 0.f);
    h0.w = fmaxf(h0.w * rstd * cg0.w + cb0.w, 0.f);
    h1.x = fmaxf(h1.x * rstd * cg1.x + cb1.x, 0.f);
    h1.y = fmaxf(h1.y * rstd * cg1.y + cb1.y, 0.f);
    h1.z = fmaxf(h1.z * rstd * cg1.z + cb1.z, 0.f);
    h1.w = fmaxf(h1.w * rstd * cg1.w + cb1.w, 0.f);
#pragma unroll
    for (int c = 0; c < 6; c++) {
        const float4* wr = reinterpret_cast<const float4*>(cw2 + c * 256);
        float4 w0 = wr[lane], w1 = wr[lane + 32];
        float p = h0.x * w0.x + h0.y * w0.y + h0.z * w0.z + h0.w * w0.w
                + h1.x * w1.x + h1.y * w1.y + h1.z * w1.z + h1.w * w1.w;
        p = warpSum(p);
        if (lane == 0) logits[(size_t)b * 6 + c] = p + cb2[c];
    }
}

// ---------------------------------------------------------------------------
extern "C" void kernel_launch(void* const* d_in, const int* in_sizes, int n_in,
                              void* d_out, int out_size)
{
    const float* rgb       = (const float*)d_in[0];
    const float* pose      = (const float*)d_in[1];
    const float* flow      = (const float*)d_in[2];
    const float* rgb_w     = (const float*)d_in[3];
    const float* rgb_b     = (const float*)d_in[4];
    const float* rgb_g     = (const float*)d_in[5];
    const float* rgb_beta  = (const float*)d_in[6];
    const float* pose_w    = (const float*)d_in[7];
    const float* pose_b    = (const float*)d_in[8];
    const float* pose_g    = (const float*)d_in[9];
    const float* pose_beta = (const float*)d_in[10];
    const float* flow_w    = (const float*)d_in[11];
    const float* flow_b    = (const float*)d_in[12];
    const float* flow_g    = (const float*)d_in[13];
    const float* flow_beta = (const float*)d_in[14];
    const float* in_w      = (const float*)d_in[15];
    const float* in_b      = (const float*)d_in[16];
    const float* out_w     = (const float*)d_in[17];
    const float* out_b     = (const float*)d_in[18];
    const float* gw1       = (const float*)d_in[19];
    const float* gb1       = (const float*)d_in[20];
    const float* gw2       = (const float*)d_in[21];
    const float* gb2       = (const float*)d_in[22];
    const float* cw1       = (const float*)d_in[23];
    const float* cb1       = (const float*)d_in[24];
    const float* cg        = (const float*)d_in[25];
    const float* cbeta     = (const float*)d_in[26];
    const float* cw2       = (const float*)d_in[27];
    const float* cb2       = (const float*)d_in[28];

    float* out = (float*)d_out;                 // [B*6 logits | B*3 gate]
    float* logits_out = out;
    float* gate_out   = out + (size_t)BATCH * 6;

    __half *rgb_h, *pose_h, *flow_h, *proj_h, *qkv_h, *ctx_h, *att_h, *gh_h, *fused_h;
    __half *rgbw_h, *posew_h, *floww_h, *inw_h, *outw_h, *gw1_h, *cw1_h;
    float *chid;
    cudaGetSymbolAddress((void**)&rgb_h,   g_rgb_h);
    cudaGetSymbolAddress((void**)&pose_h,  g_pose_h);
    cudaGetSymbolAddress((void**)&flow_h,  g_flow_h);
    cudaGetSymbolAddress((void**)&proj_h,  g_proj_h);
    cudaGetSymbolAddress((void**)&qkv_h,   g_qkv_h);
    cudaGetSymbolAddress((void**)&ctx_h,   g_ctx_h);
    cudaGetSymbolAddress((void**)&att_h,   g_att_h);
    cudaGetSymbolAddress((void**)&gh_h,    g_gh_h);
    cudaGetSymbolAddress((void**)&fused_h, g_fused_h);
    cudaGetSymbolAddress((void**)&rgbw_h,  g_rgbw_h);
    cudaGetSymbolAddress((void**)&posew_h, g_posew_h);
    cudaGetSymbolAddress((void**)&floww_h, g_floww_h);
    cudaGetSymbolAddress((void**)&inw_h,   g_inw_h);
    cudaGetSymbolAddress((void**)&outw_h,  g_outw_h);
    cudaGetSymbolAddress((void**)&gw1_h,   g_gw1_h);
    cudaGetSymbolAddress((void**)&cw1_h,   g_cw1_h);
    cudaGetSymbolAddress((void**)&chid, g_chid);

    cudaFuncSetAttribute((const void*)gemm_h<0, __half>,
        cudaFuncAttributeMaxDynamicSharedMemorySize, H_SMEM);
    cudaFuncSetAttribute((const void*)gemm_h<0, float>,
        cudaFuncAttributeMaxDynamicSharedMemorySize, H_SMEM);
    cudaFuncSetAttribute((const void*)gemm_batch,
        cudaFuncAttributeMaxDynamicSharedMemorySize, H_SMEM);

    // 0) one fused fp32 -> fp16 convert (inputs + GEMM weights)
    {
        CvtArgs ca;
        ca.src[0] = rgb;    ca.dst[0] = rgb_h;
        ca.src[1] = pose;   ca.dst[1] = pose_h;
        ca.src[2] = flow;   ca.dst[2] = flow_h;
        ca.src[3] = rgb_w;  ca.dst[3] = rgbw_h;
        ca.src[4] = pose_w; ca.dst[4] = posew_h;
        ca.src[5] = flow_w; ca.dst[5] = floww_h;
        ca.src[6] = in_w;   ca.dst[6] = inw_h;
        ca.src[7] = out_w;  ca.dst[7] = outw_h;
        ca.src[8] = gw1;    ca.dst[8] = gw1_h;
        ca.src[9] = cw1;    ca.dst[9] = cw1_h;
        f2h_all<<<(unsigned)((CVT_TOTAL8 + 255) / 256), 256>>>(ca);
    }

    // 1) per-modality projections, ONE launch (longest K first for tail)
    {
        BatchDesc d;
        d.nops = 3;
        // flow (K=1024)
        d.A[0] = flow_h;  d.W[0] = floww_h; d.bias[0] = flow_b;
        d.C[0] = proj_h + 1024; d.K[0] = 1024; d.ldc[0] = 1536;
        d.relu[0] = 0; d.gx[0] = 4; d.cnt[0] = 512;
        // rgb (K=768)
        d.A[1] = rgb_h;   d.W[1] = rgbw_h;  d.bias[1] = rgb_b;
        d.C[1] = proj_h + 0;    d.K[1] = 768;  d.ldc[1] = 1536;
        d.relu[1] = 0; d.gx[1] = 4; d.cnt[1] = 512;
        // pose (K=640)
        d.A[2] = pose_h;  d.W[2] = posew_h; d.bias[2] = pose_b;
        d.C[2] = proj_h + 512;  d.K[2] = 640;  d.ldc[2] = 1536;
        d.relu[2] = 0; d.gx[2] = 4; d.cnt[2] = 512;
        gemm_batch<<<1536, 256, H_SMEM>>>(d);
    }
    // 2) LN + ReLU per (b, modality) row (in-place fp16)
    ln_relu3_h<<<BATCH * 3, 128>>>(proj_h, rgb_g, rgb_beta, pose_g, pose_beta,
                                   flow_g, flow_beta);
    // 3) gate MLP layer 1 + packed QKV projection, ONE launch (gate1 first:
    //    its K=1536 CTAs are 3x longer, start them early)
    {
        BatchDesc d;
        d.nops = 2;
        // gate1: (16384 x 1536) x (512 x 1536)^T -> gh (ReLU)
        d.A[0] = proj_h; d.W[0] = gw1_h; d.bias[0] = gb1;
        d.C[0] = gh_h;   d.K[0] = 1536;  d.ldc[0] = 512;
        d.relu[0] = 1; d.gx[0] = 4; d.cnt[0] = 512;
        // qkv: (49152 x 512) x (1536 x 512)^T -> qkv_h
        d.A[1] = proj_h; d.W[1] = inw_h; d.bias[1] = in_b;
        d.C[1] = qkv_h;  d.K[1] = 512;   d.ldc[1] = 1536;
        d.relu[1] = 0; d.gx[1] = 12; d.cnt[1] = 4608;
        gemm_batch<<<5120, 256, H_SMEM>>>(d);
    }
    // 4) 3-token 8-head attention -> fp16 ctx
    attn3_h<<<BATCH * 8 / 4, 128>>>(qkv_h, ctx_h);
    // 5) attention out-projection -> fp16 att
    gemm_h<0, __half><<<dim3(4, 384), 256, H_SMEM>>>(ctx_h, outw_h, out_b, att_h, 512, 512);
    // 6) gate logits + softmax + weighted fusion -> fp16 fused + gate out
    gate_fuse_h<<<BATCH, 128>>>(gh_h, gw2, gb2, att_h, fused_h, gate_out);
    // 7) classifier layer 1 -> fp32 chid
    gemm_h<0, float><<<dim3(2, 128), 256, H_SMEM>>>(fused_h, cw1_h, cb1, chid, 512, 256);
    // 8) LN + ReLU + 6-way head
    cls_head<<<BATCH / 4, 128>>>(chid, cg, cbeta, cw2, cb2, logits_out);
}

// round 14
// speedup vs baseline: 1.4223x; 1.1148x over previous
#include <cuda_runtime.h>
#include <cuda_fp16.h>
#include <cstdint>
#include <math.h>

// ---------------------------------------------------------------------------
// AttentionFusion on GB300 (sm_103): fp16 mma.sync (m16n8k16) GEMMs via
// ldmatrix, 128x128 CTA tile / 2 CTAs/SM, batched-GEMM megakernel, and
// gate-before-projection algebra (fused = (sum_s g_s ctx_s) @ Wout + b).
// B=16384, E=512, H=8, HD=64, NC=6.
// ---------------------------------------------------------------------------

#define BATCH 16384

// fp16 scratch
__device__ __half g_rgb_h [BATCH * 768];
__device__ __half g_pose_h[BATCH * 640];
__device__ __half g_flow_h[BATCH * 1024];
__device__ __half g_proj_h[BATCH * 1536];   // (B,3,512), post-LN in-place
__device__ __half g_qkv_h [BATCH * 4608];   // (B*3, 1536) rows
__device__ __half g_wctx_h[BATCH * 512];    // gate-weighted context
__device__ __half g_gh_h  [BATCH * 512];
__device__ __half g_fused_h[BATCH * 512];
// fp16 weights
__device__ __half g_rgbw_h [512 * 768];
__device__ __half g_posew_h[512 * 640];
__device__ __half g_floww_h[512 * 1024];
__device__ __half g_inw_h  [1536 * 512];
__device__ __half g_outw_h [512 * 512];
__device__ __half g_gw1_h  [512 * 1536];
__device__ __half g_cw1_h  [256 * 512];
// fp32 scratch
__device__ float g_chid[BATCH * 256];

__device__ __forceinline__ uint32_t smem_u32(const void* p) {
    uint32_t a;
    asm("{ .reg .u64 t; cvta.to.shared.u64 t, %1; cvt.u32.u64 %0, t; }"
        : "=r"(a) : "l"(p));
    return a;
}

// ---------------------------------------------------------------------------
// single fused fp32->fp16 convert over all inputs+weights
// ---------------------------------------------------------------------------
struct CvtArgs {
    const float* src[10];
    __half* dst[10];
};
__device__ __constant__ const long CVT_END[10] = {
    12582912,              // rgb     16384*768
    23068672,              // pose    +16384*640
    39845888,              // flow    +16384*1024
    40239104,              // rgbw    +512*768
    40566784,              // posew   +512*640
    41091072,              // floww   +512*1024
    41877504,              // inw     +1536*512
    42139648,              // outw    +512*512
    42926080,              // gw1     +512*1536
    43057152               // cw1     +256*512
};
constexpr long CVT_TOTAL8 = 43057152 / 8;

__global__ void __launch_bounds__(256) f2h_all(CvtArgs args)
{
    long v = (long)blockIdx.x * 256 + threadIdx.x;
    if (v >= CVT_TOTAL8) return;
    long i = v * 8;
    int s = 0;
#pragma unroll
    for (int k = 0; k < 10; k++)
        if (i >= CVT_END[k]) s = k + 1;
    long base = (s == 0) ? 0 : CVT_END[s - 1];
    long off = i - base;
    const float* in = args.src[s] + off;
    __half* out = args.dst[s] + off;
    float4 v0 = *reinterpret_cast<const float4*>(in);
    float4 v1 = *reinterpret_cast<const float4*>(in + 4);
    union { uint4 u; __half2 h[4]; } pk;
    pk.h[0] = __floats2half2_rn(v0.x, v0.y);
    pk.h[1] = __floats2half2_rn(v0.z, v0.w);
    pk.h[2] = __floats2half2_rn(v1.x, v1.y);
    pk.h[3] = __floats2half2_rn(v1.z, v1.w);
    *reinterpret_cast<uint4*>(out) = pk.u;
}

// ---------------------------------------------------------------------------
// shared GEMM core: C[M,N] = A[M,K] * W[N,K]^T + bias (torch Linear layout)
// BM=BN=128, BK=64 halves, 256 threads = 8 warps (4m x 2n), warp tile 32x64.
// 3-stage cp.async pipeline, single __syncthreads per chunk, SW128 swizzle,
// ldmatrix.x4, mma.m16n8k16, 2 CTAs/SM.
// ---------------------------------------------------------------------------
constexpr int H_STAGEB = 32768;               // bytes per stage (A 16K + B 16K)
constexpr int H_SMEM   = 3 * H_STAGEB;        // 98304

__device__ __forceinline__ void storePair(float v0, float v1, __half* p) {
    *reinterpret_cast<__half2*>(p) = __floats2half2_rn(v0, v1);
}
__device__ __forceinline__ void storePair(float v0, float v1, float* p) {
    *reinterpret_cast<float2*>(p) = make_float2(v0, v1);
}

template<typename OT>
__device__ __forceinline__ void gemm_core(
    const __half* __restrict__ A, const __half* __restrict__ W,
    const float* __restrict__ bias, OT* __restrict__ C,
    int K, int ldc, int relu, int bm, int bn, uint32_t sb)
{
    const int tid = threadIdx.x;
    const int wid = tid >> 5, lane = tid & 31;
    const int q  = lane >> 2, kr = lane & 3;
    const int wm = wid & 3,  wn = wid >> 2;

    // cp.async: thread covers 64B (4 x 16B segs) of one 128B row, A and B
    const int lrow = tid >> 1;
    const int hoff = (tid & 1) * 32;               // halves
    const __half* Arow = A + (size_t)(bm + lrow) * K + hoff;
    const __half* Wrow = W + (size_t)(bn + lrow) * K + hoff;
    uint32_t dstA[4];
    {
        const uint32_t rowb = (uint32_t)lrow * 128;
        const uint32_t m = (lrow & 7) << 4;
#pragma unroll
        for (int i = 0; i < 4; i++) {
            const uint32_t seg = (tid & 1) * 4 + i;
            dstA[i] = sb + rowb + ((seg * 16) ^ m);
        }
    }

#define LOAD_CHUNK(kc_) do {                                                  \
        const uint32_t st_ = ((kc_) % 3) * H_STAGEB;                          \
        const __half* ap_ = Arow + (size_t)(kc_) * 64;                        \
        const __half* wp_ = Wrow + (size_t)(kc_) * 64;                        \
        _Pragma("unroll")                                                     \
        for (int i = 0; i < 4; i++)                                           \
            asm volatile("cp.async.cg.shared.global [%0], [%1], 16;"          \
                :: "r"(dstA[i] + st_), "l"(ap_ + i * 8) : "memory");          \
        _Pragma("unroll")                                                     \
        for (int i = 0; i < 4; i++)                                           \
            asm volatile("cp.async.cg.shared.global [%0], [%1], 16;"          \
                :: "r"(dstA[i] + st_ + 16384), "l"(wp_ + i * 8) : "memory");  \
        asm volatile("cp.async.commit_group;" ::: "memory");                  \
    } while (0)

    const int KC = K >> 6;
    // prologue: (stages-1) chunks in flight
    LOAD_CHUNK(0); LOAD_CHUNK(1);

    // ldmatrix address components (per thread)
    uint32_t rowbA[2], mAr[2], rowbB[4], mBr[4];
    const uint32_t colA0 = (lane >> 4) * 16;             // bytes
    const uint32_t colB0 = ((lane >> 3) & 1) * 16;       // bytes
#pragma unroll
    for (int t = 0; t < 2; t++) {
        const uint32_t r = wm * 32 + t * 16 + (lane & 15);
        rowbA[t] = r * 128; mAr[t] = (r & 7) << 4;
    }
#pragma unroll
    for (int jj = 0; jj < 4; jj++) {
        const uint32_t r = wn * 64 + jj * 16 + (lane & 7) + ((lane >> 4) & 1) * 8;
        rowbB[jj] = r * 128; mBr[jj] = (r & 7) << 4;
    }

    float c[2][8][4];
#pragma unroll
    for (int t = 0; t < 2; t++)
#pragma unroll
        for (int j = 0; j < 8; j++)
#pragma unroll
            for (int r = 0; r < 4; r++) c[t][j][r] = 0.f;

    for (int kc = 0; kc < KC; kc++) {
        // chunk kc resident when <=1 newer groups outstanding
        asm volatile("cp.async.wait_group 1;" ::: "memory");
        __syncthreads();
        // issue next loads BEFORE compute: stage (kc+2)%3 was consumed at
        // iteration kc-1; the barrier above proves all warps left it.
        const int kn = kc + 2;
        if (kn < KC) { LOAD_CHUNK(kn); }
        else asm volatile("cp.async.commit_group;" ::: "memory");

        const uint32_t As = sb + (kc % 3) * H_STAGEB;
        const uint32_t Bs = As + 16384;
#pragma unroll
        for (int ks = 0; ks < 4; ks++) {
            uint32_t a[2][4], b[4][4];
#pragma unroll
            for (int t = 0; t < 2; t++) {
                const uint32_t ad = As + rowbA[t] + ((colA0 + ks * 32) ^ mAr[t]);
                asm volatile(
                    "ldmatrix.sync.aligned.m8n8.x4.shared.b16 {%0,%1,%2,%3}, [%4];"
                    : "=r"(a[t][0]), "=r"(a[t][1]), "=r"(a[t][2]), "=r"(a[t][3])
                    : "r"(ad));
            }
#pragma unroll
            for (int jj = 0; jj < 4; jj++) {
                const uint32_t bd = Bs + rowbB[jj] + ((colB0 + ks * 32) ^ mBr[jj]);
                asm volatile(
                    "ldmatrix.sync.aligned.m8n8.x4.shared.b16 {%0,%1,%2,%3}, [%4];"
                    : "=r"(b[jj][0]), "=r"(b[jj][1]), "=r"(b[jj][2]), "=r"(b[jj][3])
                    : "r"(bd));
            }
#pragma unroll
            for (int t = 0; t < 2; t++)
#pragma unroll
                for (int j = 0; j < 8; j++) {
                    const int jj = j >> 1, lo = (j & 1) * 2;
                    asm volatile(
                        "mma.sync.aligned.m16n8k16.row.col.f32.f16.f16.f32 "
                        "{%0,%1,%2,%3}, {%4,%5,%6,%7}, {%8,%9}, {%0,%1,%2,%3};"
                        : "+f"(c[t][j][0]), "+f"(c[t][j][1]),
                          "+f"(c[t][j][2]), "+f"(c[t][j][3])
                        : "r"(a[t][0]), "r"(a[t][1]), "r"(a[t][2]), "r"(a[t][3]),
                          "r"(b[jj][lo]), "r"(b[jj][lo + 1]));
                }
        }
    }
#undef LOAD_CHUNK

    // epilogue: bias (+ReLU, uniform runtime branch)
#pragma unroll
    for (int t = 0; t < 2; t++) {
        const int r0 = bm + wm * 32 + t * 16 + q;
#pragma unroll
        for (int j = 0; j < 8; j++) {
            const int col = bn + wn * 64 + j * 8 + (kr << 1);
            const float b0 = bias[col], b1 = bias[col + 1];
            float v00 = c[t][j][0] + b0, v01 = c[t][j][1] + b1;
            float v10 = c[t][j][2] + b0, v11 = c[t][j][3] + b1;
            if (relu) {
                v00 = fmaxf(v00, 0.f); v01 = fmaxf(v01, 0.f);
                v10 = fmaxf(v10, 0.f); v11 = fmaxf(v11, 0.f);
            }
            storePair(v00, v01, C + (size_t)r0 * ldc + col);
            storePair(v10, v11, C + (size_t)(r0 + 8) * ldc + col);
        }
    }
}

// single-op GEMM wrapper (outproj half, cls1 float)
template<int RELU, typename OT>
__global__ void __launch_bounds__(256, 2) gemm_h(
    const __half* __restrict__ A, const __half* __restrict__ W,
    const float* __restrict__ bias, OT* __restrict__ C,
    int K, int ldc)
{
    extern __shared__ __align__(16) char smem[];
    gemm_core<OT>(A, W, bias, C, K, ldc, RELU,
                  blockIdx.y * 128, blockIdx.x * 128, smem_u32(smem));
}

// batched GEMM: up to 3 ops in one launch; linear blockIdx -> (op, bx, by)
struct BatchDesc {
    const __half* A[3];
    const __half* W[3];
    const float*  bias[3];
    __half*       C[3];
    int K[3], ldc[3], relu[3], gx[3], cnt[3];
    int nops;
};

__global__ void __launch_bounds__(256, 2) gemm_batch(BatchDesc d)
{
    extern __shared__ __align__(16) char smem[];
    int id = blockIdx.x;
    int op = 0;
    while (op + 1 < d.nops && id >= d.cnt[op]) { id -= d.cnt[op]; ++op; }
    const int gx = d.gx[op];
    const int bx = id % gx, by = id / gx;
    gemm_core<__half>(d.A[op], d.W[op], d.bias[op], d.C[op],
                      d.K[op], d.ldc[op], d.relu[op],
                      by * 128, bx * 128, smem_u32(smem));
}

// ---------------------------------------------------------------------------
// elementwise / small kernels
// ---------------------------------------------------------------------------
__device__ __forceinline__ float warpSum(float v) {
#pragma unroll
    for (int o = 16; o > 0; o >>= 1) v += __shfl_xor_sync(0xffffffffu, v, o);
    return v;
}

__device__ __forceinline__ float blockSum128(float v, float* sred) {
    int lane = threadIdx.x & 31, w = threadIdx.x >> 5;
    v = warpSum(v);
    __syncthreads();
    if (lane == 0) sred[w] = v;
    __syncthreads();
    return sred[0] + sred[1] + sred[2] + sred[3];
}

// in-place LN+ReLU on fp16 rows of 512; modality = row % 3
__global__ void __launch_bounds__(128) ln_relu3_h(
    __half* __restrict__ x,
    const float* __restrict__ g0, const float* __restrict__ be0,
    const float* __restrict__ g1, const float* __restrict__ be1,
    const float* __restrict__ g2, const float* __restrict__ be2)
{
    __shared__ float sred[4];
    int row = blockIdx.x;
    int s = row % 3;
    const float* g  = (s == 0) ? g0 : (s == 1) ? g1 : g2;
    const float* be = (s == 0) ? be0 : (s == 1) ? be1 : be2;
    __half* xr = x + (size_t)row * 512;
    int t = threadIdx.x;
    union { uint2 u; __half2 h[2]; } pk;
    pk.u = *reinterpret_cast<const uint2*>(xr + 4 * t);
    float2 f0 = __half22float2(pk.h[0]), f1 = __half22float2(pk.h[1]);
    float sum = blockSum128(f0.x + f0.y + f1.x + f1.y, sred);
    float mean = sum * (1.f / 512.f);
    float dx = f0.x - mean, dy = f0.y - mean, dz = f1.x - mean, dw = f1.y - mean;
    float ss = blockSum128(dx * dx + dy * dy + dz * dz + dw * dw, sred);
    float rstd = rsqrtf(ss * (1.f / 512.f) + 1e-5f);
    float4 gv = reinterpret_cast<const float4*>(g)[t];
    float4 bv = reinterpret_cast<const float4*>(be)[t];
    float ox = fmaxf(dx * rstd * gv.x + bv.x, 0.f);
    float oy = fmaxf(dy * rstd * gv.y + bv.y, 0.f);
    float oz = fmaxf(dz * rstd * gv.z + bv.z, 0.f);
    float ow = fmaxf(dw * rstd * gv.w + bv.w, 0.f);
    pk.h[0] = __floats2half2_rn(ox, oy);
    pk.h[1] = __floats2half2_rn(oz, ow);
    *reinterpret_cast<uint2*>(xr + 4 * t) = pk.u;
}

// ---------------------------------------------------------------------------
// Fused gate + attention + weighted-context kernel.  One 128-thread block
// per sample:
//   1) gate logits from gh row (3 dots of 512) + softmax -> g0,g1,g2
//   2) 3-token 8-head attention from qkv (warp handles 2 heads)
//   3) wctx = sum_i g_i * ctx_i  written directly (ctx never hits gmem)
// fused = wctx @ Wout^T + out_b afterward (sum g = 1 absorbs the bias).
// ---------------------------------------------------------------------------
__global__ void __launch_bounds__(128) attn_gate_h(
    const __half* __restrict__ qkv, const __half* __restrict__ gh,
    const float* __restrict__ gw2, const float* __restrict__ gb2,
    __half* __restrict__ wctx, float* __restrict__ gate_out)
{
    __shared__ float sred[4];
    const int b = blockIdx.x, t = threadIdx.x;
    const int lane = t & 31, warp = t >> 5;

    // --- gate softmax over 3 modality logits ---
    union { uint2 u; __half2 h[2]; } hv;
    hv.u = *reinterpret_cast<const uint2*>(gh + (size_t)b * 512 + 4 * t);
    float2 h0 = __half22float2(hv.h[0]), h1 = __half22float2(hv.h[1]);
    float l[3];
#pragma unroll
    for (int s = 0; s < 3; s++) {
        float4 w = reinterpret_cast<const float4*>(gw2 + s * 512)[t];
        l[s] = blockSum128(h0.x * w.x + h0.y * w.y + h1.x * w.z + h1.y * w.w, sred)
             + gb2[s];
    }
    float m = fmaxf(l[0], fmaxf(l[1], l[2]));
    float e0 = expf(l[0] - m), e1 = expf(l[1] - m), e2 = expf(l[2] - m);
    float inv = 1.f / (e0 + e1 + e2);
    const float g0 = e0 * inv, g1 = e1 * inv, g2 = e2 * inv;
    if (t == 0) {
        gate_out[b * 3 + 0] = g0;
        gate_out[b * 3 + 1] = g1;
        gate_out[b * 3 + 2] = g2;
    }

    // --- attention: warp w handles heads 2w, 2w+1 ---
#pragma unroll
    for (int hh = 0; hh < 2; hh++) {
        const int h = warp * 2 + hh;
        const __half* base = qkv + (size_t)b * 4608 + h * 64 + 2 * lane;
        float2 q[3], k[3], v[3];
#pragma unroll
        for (int i = 0; i < 3; i++) {
            q[i] = __half22float2(*reinterpret_cast<const __half2*>(base + i * 1536));
            k[i] = __half22float2(*reinterpret_cast<const __half2*>(base + i * 1536 + 512));
            v[i] = __half22float2(*reinterpret_cast<const __half2*>(base + i * 1536 + 1024));
        }
        float a[3][3];
#pragma unroll
        for (int i = 0; i < 3; i++)
#pragma unroll
            for (int j = 0; j < 3; j++) {
                float p = q[i].x * k[j].x + q[i].y * k[j].y;
                a[i][j] = warpSum(p) * 0.125f;      // 1/sqrt(64)
            }
        float wx = 0.f, wy = 0.f;
#pragma unroll
        for (int i = 0; i < 3; i++) {
            float mm = fmaxf(a[i][0], fmaxf(a[i][1], a[i][2]));
            float x0 = expf(a[i][0] - mm), x1 = expf(a[i][1] - mm), x2 = expf(a[i][2] - mm);
            float iv = 1.f / (x0 + x1 + x2);
            float ox = (x0 * v[0].x + x1 * v[1].x + x2 * v[2].x) * iv;
            float oy = (x0 * v[0].y + x1 * v[1].y + x2 * v[2].y) * iv;
            const float gi = (i == 0) ? g0 : (i == 1) ? g1 : g2;
            wx += gi * ox; wy += gi * oy;
        }
        *reinterpret_cast<__half2*>(wctx + (size_t)b * 512 + h * 64 + 2 * lane)
            = __floats2half2_rn(wx, wy);
    }
}

// classifier head: LN(256) + ReLU + 6-way linear; one warp per sample
__global__ void __launch_bounds__(128) cls_head(
    const float* __restrict__ chid, const float* __restrict__ cg,
    const float* __restrict__ cbeta, const float* __restrict__ cw2,
    const float* __restrict__ cb2, float* __restrict__ logits)
{
    int b = blockIdx.x * 4 + (threadIdx.x >> 5);
    int lane = threadIdx.x & 31;
    const float* hr = chid + (size_t)b * 256;
    float4 h0 = reinterpret_cast<const float4*>(hr)[lane];
    float4 h1 = reinterpret_cast<const float4*>(hr)[lane + 32];
    float sum = warpSum(h0.x + h0.y + h0.z + h0.w + h1.x + h1.y + h1.z + h1.w);
    float mean = sum * (1.f / 256.f);
    h0.x -= mean; h0.y -= mean; h0.z -= mean; h0.w -= mean;
    h1.x -= mean; h1.y -= mean; h1.z -= mean; h1.w -= mean;
    float ss = warpSum(h0.x * h0.x + h0.y * h0.y + h0.z * h0.z + h0.w * h0.w
                     + h1.x * h1.x + h1.y * h1.y + h1.z * h1.z + h1.w * h1.w);
    float rstd = rsqrtf(ss * (1.f / 256.f) + 1e-5f);
    float4 cg0 = reinterpret_cast<const float4*>(cg)[lane];
    float4 cg1 = reinterpret_cast<const float4*>(cg)[lane + 32];
    float4 cb0 = reinterpret_cast<const float4*>(cbeta)[lane];
    float4 cb1 = reinterpret_cast<const float4*>(cbeta)[lane + 32];
    h0.x = fmaxf(h0.x * rstd * cg0.x + cb0.x, 0.f);
    h0.y = fmaxf(h0.y * rstd * cg0.y + cb0.y, 0.f);
    h0.z = fmaxf(h0.z * rstd * cg0.z + cb0.z, 0.f);
    h0.w = fmaxf(h0.w * rstd * cg0.w + cb0.w, 0.f);
    h1.x = fmaxf(h1.x * rstd * cg1.x + cb1.x, 0.f);
    h1.y = fmaxf(h1.y * rstd * cg1.y + cb1.y, 0.f);
    h1.z = fmaxf(h1.z * rstd * cg1.z + cb1.z, 0.f);
    h1.w = fmaxf(h1.w * rstd * cg1.w + cb1.w, 0.f);
#pragma unroll
    for (int c = 0; c < 6; c++) {
        const float4* wr = reinterpret_cast<const float4*>(cw2 + c * 256);
        float4 w0 = wr[lane], w1 = wr[lane + 32];
        float p = h0.x * w0.x + h0.y * w0.y + h0.z * w0.z + h0.w * w0.w
                + h1.x * w1.x + h1.y * w1.y + h1.z * w1.z + h1.w * w1.w;
        p = warpSum(p);
        if (lane == 0) logits[(size_t)b * 6 + c] = p + cb2[c];
    }
}

// ---------------------------------------------------------------------------
extern "C" void kernel_launch(void* const* d_in, const int* in_sizes, int n_in,
                              void* d_out, int out_size)
{
    const float* rgb       = (const float*)d_in[0];
    const float* pose      = (const float*)d_in[1];
    const float* flow      = (const float*)d_in[2];
    const float* rgb_w     = (const float*)d_in[3];
    const float* rgb_b     = (const float*)d_in[4];
    const float* rgb_g     = (const float*)d_in[5];
    const float* rgb_beta  = (const float*)d_in[6];
    const float* pose_w    = (const float*)d_in[7];
    const float* pose_b    = (const float*)d_in[8];
    const float* pose_g    = (const float*)d_in[9];
    const float* pose_beta = (const float*)d_in[10];
    const float* flow_w    = (const float*)d_in[11];
    const float* flow_b    = (const float*)d_in[12];
    const float* flow_g    = (const float*)d_in[13];
    const float* flow_beta = (const float*)d_in[14];
    const float* in_w      = (const float*)d_in[15];
    const float* in_b      = (const float*)d_in[16];
    const float* out_w     = (const float*)d_in[17];
    const float* out_b     = (const float*)d_in[18];
    const float* gw1       = (const float*)d_in[19];
    const float* gb1       = (const float*)d_in[20];
    const float* gw2       = (const float*)d_in[21];
    const float* gb2       = (const float*)d_in[22];
    const float* cw1       = (const float*)d_in[23];
    const float* cb1       = (const float*)d_in[24];
    const float* cg        = (const float*)d_in[25];
    const float* cbeta     = (const float*)d_in[26];
    const float* cw2       = (const float*)d_in[27];
    const float* cb2       = (const float*)d_in[28];

    float* out = (float*)d_out;                 // [B*6 logits | B*3 gate]
    float* logits_out = out;
    float* gate_out   = out + (size_t)BATCH * 6;

    __half *rgb_h, *pose_h, *flow_h, *proj_h, *qkv_h, *wctx_h, *gh_h, *fused_h;
    __half *rgbw_h, *posew_h, *floww_h, *inw_h, *outw_h, *gw1_h, *cw1_h;
    float *chid;
    cudaGetSymbolAddress((void**)&rgb_h,   g_rgb_h);
    cudaGetSymbolAddress((void**)&pose_h,  g_pose_h);
    cudaGetSymbolAddress((void**)&flow_h,  g_flow_h);
    cudaGetSymbolAddress((void**)&proj_h,  g_proj_h);
    cudaGetSymbolAddress((void**)&qkv_h,   g_qkv_h);
    cudaGetSymbolAddress((void**)&wctx_h,  g_wctx_h);
    cudaGetSymbolAddress((void**)&gh_h,    g_gh_h);
    cudaGetSymbolAddress((void**)&fused_h, g_fused_h);
    cudaGetSymbolAddress((void**)&rgbw_h,  g_rgbw_h);
    cudaGetSymbolAddress((void**)&posew_h, g_posew_h);
    cudaGetSymbolAddress((void**)&floww_h, g_floww_h);
    cudaGetSymbolAddress((void**)&inw_h,   g_inw_h);
    cudaGetSymbolAddress((void**)&outw_h,  g_outw_h);
    cudaGetSymbolAddress((void**)&gw1_h,   g_gw1_h);
    cudaGetSymbolAddress((void**)&cw1_h,   g_cw1_h);
    cudaGetSymbolAddress((void**)&chid, g_chid);

    cudaFuncSetAttribute((const void*)gemm_h<0, __half>,
        cudaFuncAttributeMaxDynamicSharedMemorySize, H_SMEM);
    cudaFuncSetAttribute((const void*)gemm_h<0, float>,
        cudaFuncAttributeMaxDynamicSharedMemorySize, H_SMEM);
    cudaFuncSetAttribute((const void*)gemm_batch,
        cudaFuncAttributeMaxDynamicSharedMemorySize, H_SMEM);

    // 0) one fused fp32 -> fp16 convert (inputs + GEMM weights)
    {
        CvtArgs ca;
        ca.src[0] = rgb;    ca.dst[0] = rgb_h;
        ca.src[1] = pose;   ca.dst[1] = pose_h;
        ca.src[2] = flow;   ca.dst[2] = flow_h;
        ca.src[3] = rgb_w;  ca.dst[3] = rgbw_h;
        ca.src[4] = pose_w; ca.dst[4] = posew_h;
        ca.src[5] = flow_w; ca.dst[5] = floww_h;
        ca.src[6] = in_w;   ca.dst[6] = inw_h;
        ca.src[7] = out_w;  ca.dst[7] = outw_h;
        ca.src[8] = gw1;    ca.dst[8] = gw1_h;
        ca.src[9] = cw1;    ca.dst[9] = cw1_h;
        f2h_all<<<(unsigned)((CVT_TOTAL8 + 255) / 256), 256>>>(ca);
    }

    // 1) per-modality projections, ONE launch (longest K first for tail)
    {
        BatchDesc d;
        d.nops = 3;
        // flow (K=1024)
        d.A[0] = flow_h;  d.W[0] = floww_h; d.bias[0] = flow_b;
        d.C[0] = proj_h + 1024; d.K[0] = 1024; d.ldc[0] = 1536;
        d.relu[0] = 0; d.gx[0] = 4; d.cnt[0] = 512;
        // rgb (K=768)
        d.A[1] = rgb_h;   d.W[1] = rgbw_h;  d.bias[1] = rgb_b;
        d.C[1] = proj_h + 0;    d.K[1] = 768;  d.ldc[1] = 1536;
        d.relu[1] = 0; d.gx[1] = 4; d.cnt[1] = 512;
        // pose (K=640)
        d.A[2] = pose_h;  d.W[2] = posew_h; d.bias[2] = pose_b;
        d.C[2] = proj_h + 512;  d.K[2] = 640;  d.ldc[2] = 1536;
        d.relu[2] = 0; d.gx[2] = 4; d.cnt[2] = 512;
        gemm_batch<<<1536, 256, H_SMEM>>>(d);
    }
    // 2) LN + ReLU per (b, modality) row (in-place fp16)
    ln_relu3_h<<<BATCH * 3, 128>>>(proj_h, rgb_g, rgb_beta, pose_g, pose_beta,
                                   flow_g, flow_beta);
    // 3) gate MLP layer 1 + packed QKV projection, ONE launch (gate1 first:
    //    its K=1536 CTAs are 3x longer, start them early)
    {
        BatchDesc d;
        d.nops = 2;
        // gate1: (16384 x 1536) x (512 x 1536)^T -> gh (ReLU)
        d.A[0] = proj_h; d.W[0] = gw1_h; d.bias[0] = gb1;
        d.C[0] = gh_h;   d.K[0] = 1536;  d.ldc[0] = 512;
        d.relu[0] = 1; d.gx[0] = 4; d.cnt[0] = 512;
        // qkv: (49152 x 512) x (1536 x 512)^T -> qkv_h
        d.A[1] = proj_h; d.W[1] = inw_h; d.bias[1] = in_b;
        d.C[1] = qkv_h;  d.K[1] = 512;   d.ldc[1] = 1536;
        d.relu[1] = 0; d.gx[1] = 12; d.cnt[1] = 4608;
        gemm_batch<<<5120, 256, H_SMEM>>>(d);
    }
    // 4) fused gate softmax + attention + weighted context -> wctx, gate_out
    attn_gate_h<<<BATCH, 128>>>(qkv_h, gh_h, gw2, gb2, wctx_h, gate_out);
    // 5) out-projection on WEIGHTED context (3x fewer FLOPs than per-token)
    gemm_h<0, __half><<<dim3(4, 128), 256, H_SMEM>>>(wctx_h, outw_h, out_b, fused_h, 512, 512);
    // 6) classifier layer 1 -> fp32 chid
    gemm_h<0, float><<<dim3(2, 128), 256, H_SMEM>>>(fused_h, cw1_h, cb1, chid, 512, 256);
    // 7) LN + ReLU + 6-way head
    cls_head<<<BATCH / 4, 128>>>(chid, cg, cbeta, cw2, cb2, logits_out);
}

// round 16
// speedup vs baseline: 1.4589x; 1.0257x over previous
#include <cuda_runtime.h>
#include <cuda_fp16.h>
#include <cstdint>
#include <math.h>

// ---------------------------------------------------------------------------
// AttentionFusion on GB300 (sm_103): fp16 mma.sync (m16n8k16) GEMMs via
// ldmatrix with chunk-wide A-fragment hoist, 128x128 tile / 2 CTAs/SM,
// batched-GEMM megakernel, gate-before-projection algebra.
// B=16384, E=512, H=8, HD=64, NC=6.
// ---------------------------------------------------------------------------

#define BATCH 16384

// fp16 scratch
__device__ __half g_rgb_h [BATCH * 768];
__device__ __half g_pose_h[BATCH * 640];
__device__ __half g_flow_h[BATCH * 1024];
__device__ __half g_proj_h[BATCH * 1536];   // (B,3,512), post-LN in-place
__device__ __half g_qkv_h [BATCH * 4608];   // (B*3, 1536) rows
__device__ __half g_wctx_h[BATCH * 512];    // gate-weighted context
__device__ __half g_gh_h  [BATCH * 512];
__device__ __half g_fused_h[BATCH * 512];
// fp16 weights
__device__ __half g_rgbw_h [512 * 768];
__device__ __half g_posew_h[512 * 640];
__device__ __half g_floww_h[512 * 1024];
__device__ __half g_inw_h  [1536 * 512];
__device__ __half g_outw_h [512 * 512];
__device__ __half g_gw1_h  [512 * 1536];
__device__ __half g_cw1_h  [256 * 512];
// fp32 scratch
__device__ float g_chid[BATCH * 256];

__device__ __forceinline__ uint32_t smem_u32(const void* p) {
    uint32_t a;
    asm("{ .reg .u64 t; cvta.to.shared.u64 t, %1; cvt.u32.u64 %0, t; }"
        : "=r"(a) : "l"(p));
    return a;
}

// ---------------------------------------------------------------------------
// single fused fp32->fp16 convert over all inputs+weights
// ---------------------------------------------------------------------------
struct CvtArgs {
    const float* src[10];
    __half* dst[10];
};
__device__ __constant__ const long CVT_END[10] = {
    12582912,              // rgb     16384*768
    23068672,              // pose    +16384*640
    39845888,              // flow    +16384*1024
    40239104,              // rgbw    +512*768
    40566784,              // posew   +512*640
    41091072,              // floww   +512*1024
    41877504,              // inw     +1536*512
    42139648,              // outw    +512*512
    42926080,              // gw1     +512*1536
    43057152               // cw1     +256*512
};
constexpr long CVT_TOTAL8 = 43057152 / 8;

__global__ void __launch_bounds__(256) f2h_all(CvtArgs args)
{
    long v = (long)blockIdx.x * 256 + threadIdx.x;
    if (v >= CVT_TOTAL8) return;
    long i = v * 8;
    int s = 0;
#pragma unroll
    for (int k = 0; k < 10; k++)
        if (i >= CVT_END[k]) s = k + 1;
    long base = (s == 0) ? 0 : CVT_END[s - 1];
    long off = i - base;
    const float* in = args.src[s] + off;
    __half* out = args.dst[s] + off;
    float4 v0 = *reinterpret_cast<const float4*>(in);
    float4 v1 = *reinterpret_cast<const float4*>(in + 4);
    union { uint4 u; __half2 h[4]; } pk;
    pk.h[0] = __floats2half2_rn(v0.x, v0.y);
    pk.h[1] = __floats2half2_rn(v0.z, v0.w);
    pk.h[2] = __floats2half2_rn(v1.x, v1.y);
    pk.h[3] = __floats2half2_rn(v1.z, v1.w);
    *reinterpret_cast<uint4*>(out) = pk.u;
}

// ---------------------------------------------------------------------------
// shared GEMM core: C[M,N] = A[M,K] * W[N,K]^T + bias (torch Linear layout)
// BM=BN=128, BK=64 halves, 256 threads = 8 warps (4m x 2n), warp tile 32x64.
// 3-stage cp.async pipeline, single __syncthreads per chunk, SW128 swizzle,
// ldmatrix.x4, mma.m16n8k16, 2 CTAs/SM.  All A fragments of a chunk are
// hoisted ahead of the ks-loop so only B's LDSM latency stays exposed.
// ---------------------------------------------------------------------------
constexpr int H_STAGEB = 32768;               // bytes per stage (A 16K + B 16K)
constexpr int H_SMEM   = 3 * H_STAGEB;        // 98304

__device__ __forceinline__ void storePair(float v0, float v1, __half* p) {
    *reinterpret_cast<__half2*>(p) = __floats2half2_rn(v0, v1);
}
__device__ __forceinline__ void storePair(float v0, float v1, float* p) {
    *reinterpret_cast<float2*>(p) = make_float2(v0, v1);
}

template<typename OT>
__device__ __forceinline__ void gemm_core(
    const __half* __restrict__ A, const __half* __restrict__ W,
    const float* __restrict__ bias, OT* __restrict__ C,
    int K, int ldc, int relu, int bm, int bn, uint32_t sb)
{
    const int tid = threadIdx.x;
    const int wid = tid >> 5, lane = tid & 31;
    const int q  = lane >> 2, kr = lane & 3;
    const int wm = wid & 3,  wn = wid >> 2;

    // cp.async: thread covers 64B (4 x 16B segs) of one 128B row, A and B
    const int lrow = tid >> 1;
    const int hoff = (tid & 1) * 32;               // halves
    const __half* Arow = A + (size_t)(bm + lrow) * K + hoff;
    const __half* Wrow = W + (size_t)(bn + lrow) * K + hoff;
    uint32_t dstA[4];
    {
        const uint32_t rowb = (uint32_t)lrow * 128;
        const uint32_t m = (lrow & 7) << 4;
#pragma unroll
        for (int i = 0; i < 4; i++) {
            const uint32_t seg = (tid & 1) * 4 + i;
            dstA[i] = sb + rowb + ((seg * 16) ^ m);
        }
    }

#define LOAD_CHUNK(kc_) do {                                                  \
        const uint32_t st_ = ((kc_) % 3) * H_STAGEB;                          \
        const __half* ap_ = Arow + (size_t)(kc_) * 64;                        \
        const __half* wp_ = Wrow + (size_t)(kc_) * 64;                        \
        _Pragma("unroll")                                                     \
        for (int i = 0; i < 4; i++)                                           \
            asm volatile("cp.async.cg.shared.global [%0], [%1], 16;"          \
                :: "r"(dstA[i] + st_), "l"(ap_ + i * 8) : "memory");          \
        _Pragma("unroll")                                                     \
        for (int i = 0; i < 4; i++)                                           \
            asm volatile("cp.async.cg.shared.global [%0], [%1], 16;"          \
                :: "r"(dstA[i] + st_ + 16384), "l"(wp_ + i * 8) : "memory");  \
        asm volatile("cp.async.commit_group;" ::: "memory");                  \
    } while (0)

    const int KC = K >> 6;
    // prologue: (stages-1) chunks in flight
    LOAD_CHUNK(0); LOAD_CHUNK(1);

    // ldmatrix address components (per thread)
    uint32_t rowbA[2], mAr[2], rowbB[4], mBr[4];
    const uint32_t colA0 = (lane >> 4) * 16;             // bytes
    const uint32_t colB0 = ((lane >> 3) & 1) * 16;       // bytes
#pragma unroll
    for (int t = 0; t < 2; t++) {
        const uint32_t r = wm * 32 + t * 16 + (lane & 15);
        rowbA[t] = r * 128; mAr[t] = (r & 7) << 4;
    }
#pragma unroll
    for (int jj = 0; jj < 4; jj++) {
        const uint32_t r = wn * 64 + jj * 16 + (lane & 7) + ((lane >> 4) & 1) * 8;
        rowbB[jj] = r * 128; mBr[jj] = (r & 7) << 4;
    }

    float c[2][8][4];
#pragma unroll
    for (int t = 0; t < 2; t++)
#pragma unroll
        for (int j = 0; j < 8; j++)
#pragma unroll
            for (int r = 0; r < 4; r++) c[t][j][r] = 0.f;

    for (int kc = 0; kc < KC; kc++) {
        // chunk kc resident when <=1 newer groups outstanding
        asm volatile("cp.async.wait_group 1;" ::: "memory");
        __syncthreads();
        // issue next loads BEFORE compute
        const int kn = kc + 2;
        if (kn < KC) { LOAD_CHUNK(kn); }
        else asm volatile("cp.async.commit_group;" ::: "memory");

        const uint32_t As = sb + (kc % 3) * H_STAGEB;
        const uint32_t Bs = As + 16384;

        // hoist ALL A fragments for this chunk (2 tiles x 4 ks = 32 regs)
        uint32_t a[4][2][4];
#pragma unroll
        for (int ks = 0; ks < 4; ks++)
#pragma unroll
            for (int t = 0; t < 2; t++) {
                const uint32_t ad = As + rowbA[t] + ((colA0 + ks * 32) ^ mAr[t]);
                asm volatile(
                    "ldmatrix.sync.aligned.m8n8.x4.shared.b16 {%0,%1,%2,%3}, [%4];"
                    : "=r"(a[ks][t][0]), "=r"(a[ks][t][1]),
                      "=r"(a[ks][t][2]), "=r"(a[ks][t][3])
                    : "r"(ad));
            }

#pragma unroll
        for (int ks = 0; ks < 4; ks++) {
            uint32_t b[4][4];
#pragma unroll
            for (int jj = 0; jj < 4; jj++) {
                const uint32_t bd = Bs + rowbB[jj] + ((colB0 + ks * 32) ^ mBr[jj]);
                asm volatile(
                    "ldmatrix.sync.aligned.m8n8.x4.shared.b16 {%0,%1,%2,%3}, [%4];"
                    : "=r"(b[jj][0]), "=r"(b[jj][1]), "=r"(b[jj][2]), "=r"(b[jj][3])
                    : "r"(bd));
            }
#pragma unroll
            for (int t = 0; t < 2; t++)
#pragma unroll
                for (int j = 0; j < 8; j++) {
                    const int jj = j >> 1, lo = (j & 1) * 2;
                    asm volatile(
                        "mma.sync.aligned.m16n8k16.row.col.f32.f16.f16.f32 "
                        "{%0,%1,%2,%3}, {%4,%5,%6,%7}, {%8,%9}, {%0,%1,%2,%3};"
                        : "+f"(c[t][j][0]), "+f"(c[t][j][1]),
                          "+f"(c[t][j][2]), "+f"(c[t][j][3])
                        : "r"(a[ks][t][0]), "r"(a[ks][t][1]),
                          "r"(a[ks][t][2]), "r"(a[ks][t][3]),
                          "r"(b[jj][lo]), "r"(b[jj][lo + 1]));
                }
        }
    }
#undef LOAD_CHUNK

    // epilogue: bias (+ReLU, uniform runtime branch)
#pragma unroll
    for (int t = 0; t < 2; t++) {
        const int r0 = bm + wm * 32 + t * 16 + q;
#pragma unroll
        for (int j = 0; j < 8; j++) {
            const int col = bn + wn * 64 + j * 8 + (kr << 1);
            const float b0 = bias[col], b1 = bias[col + 1];
            float v00 = c[t][j][0] + b0, v01 = c[t][j][1] + b1;
            float v10 = c[t][j][2] + b0, v11 = c[t][j][3] + b1;
            if (relu) {
                v00 = fmaxf(v00, 0.f); v01 = fmaxf(v01, 0.f);
                v10 = fmaxf(v10, 0.f); v11 = fmaxf(v11, 0.f);
            }
            storePair(v00, v01, C + (size_t)r0 * ldc + col);
            storePair(v10, v11, C + (size_t)(r0 + 8) * ldc + col);
        }
    }
}

// single-op GEMM wrapper (outproj half, cls1 float)
template<int RELU, typename OT>
__global__ void __launch_bounds__(256, 2) gemm_h(
    const __half* __restrict__ A, const __half* __restrict__ W,
    const float* __restrict__ bias, OT* __restrict__ C,
    int K, int ldc)
{
    extern __shared__ __align__(16) char smem[];
    gemm_core<OT>(A, W, bias, C, K, ldc, RELU,
                  blockIdx.y * 128, blockIdx.x * 128, smem_u32(smem));
}

// batched GEMM: up to 3 ops in one launch; linear blockIdx -> (op, bx, by)
struct BatchDesc {
    const __half* A[3];
    const __half* W[3];
    const float*  bias[3];
    __half*       C[3];
    int K[3], ldc[3], relu[3], gx[3], cnt[3];
    int nops;
};

__global__ void __launch_bounds__(256, 2) gemm_batch(BatchDesc d)
{
    extern __shared__ __align__(16) char smem[];
    int id = blockIdx.x;
    int op = 0;
    while (op + 1 < d.nops && id >= d.cnt[op]) { id -= d.cnt[op]; ++op; }
    const int gx = d.gx[op];
    const int bx = id % gx, by = id / gx;
    gemm_core<__half>(d.A[op], d.W[op], d.bias[op], d.C[op],
                      d.K[op], d.ldc[op], d.relu[op],
                      by * 128, bx * 128, smem_u32(smem));
}

// ---------------------------------------------------------------------------
// elementwise / small kernels
// ---------------------------------------------------------------------------
__device__ __forceinline__ float warpSum(float v) {
#pragma unroll
    for (int o = 16; o > 0; o >>= 1) v += __shfl_xor_sync(0xffffffffu, v, o);
    return v;
}

// reduce two values with a single barrier pair (128 threads)
__device__ __forceinline__ float2 blockSum2_128(float v0, float v1, float* sred) {
    int lane = threadIdx.x & 31, w = threadIdx.x >> 5;
#pragma unroll
    for (int o = 16; o > 0; o >>= 1) {
        v0 += __shfl_xor_sync(0xffffffffu, v0, o);
        v1 += __shfl_xor_sync(0xffffffffu, v1, o);
    }
    __syncthreads();
    if (lane == 0) { sred[w] = v0; sred[4 + w] = v1; }
    __syncthreads();
    float2 r;
    r.x = sred[0] + sred[1] + sred[2] + sred[3];
    r.y = sred[4] + sred[5] + sred[6] + sred[7];
    return r;
}

// reduce three values with a single barrier pair (128 threads)
__device__ __forceinline__ void blockSum3_128(float v0, float v1, float v2,
                                              float* sred, float out[3]) {
    int lane = threadIdx.x & 31, w = threadIdx.x >> 5;
#pragma unroll
    for (int o = 16; o > 0; o >>= 1) {
        v0 += __shfl_xor_sync(0xffffffffu, v0, o);
        v1 += __shfl_xor_sync(0xffffffffu, v1, o);
        v2 += __shfl_xor_sync(0xffffffffu, v2, o);
    }
    __syncthreads();
    if (lane == 0) { sred[w] = v0; sred[4 + w] = v1; sred[8 + w] = v2; }
    __syncthreads();
    out[0] = sred[0] + sred[1] + sred[2] + sred[3];
    out[1] = sred[4] + sred[5] + sred[6] + sred[7];
    out[2] = sred[8] + sred[9] + sred[10] + sred[11];
}

// in-place LN+ReLU on fp16 rows of 512; modality = row % 3
// single-pass variance: var = E[x^2] - mean^2
__global__ void __launch_bounds__(128) ln_relu3_h(
    __half* __restrict__ x,
    const float* __restrict__ g0, const float* __restrict__ be0,
    const float* __restrict__ g1, const float* __restrict__ be1,
    const float* __restrict__ g2, const float* __restrict__ be2)
{
    __shared__ float sred[8];
    int row = blockIdx.x;
    int s = row % 3;
    const float* g  = (s == 0) ? g0 : (s == 1) ? g1 : g2;
    const float* be = (s == 0) ? be0 : (s == 1) ? be1 : be2;
    __half* xr = x + (size_t)row * 512;
    int t = threadIdx.x;
    union { uint2 u; __half2 h[2]; } pk;
    pk.u = *reinterpret_cast<const uint2*>(xr + 4 * t);
    float2 f0 = __half22float2(pk.h[0]), f1 = __half22float2(pk.h[1]);
    float ls  = f0.x + f0.y + f1.x + f1.y;
    float lss = f0.x * f0.x + f0.y * f0.y + f1.x * f1.x + f1.y * f1.y;
    float2 r = blockSum2_128(ls, lss, sred);
    float mean = r.x * (1.f / 512.f);
    float var  = r.y * (1.f / 512.f) - mean * mean;
    float rstd = rsqrtf(var + 1e-5f);
    float dx = f0.x - mean, dy = f0.y - mean, dz = f1.x - mean, dw = f1.y - mean;
    float4 gv = reinterpret_cast<const float4*>(g)[t];
    float4 bv = reinterpret_cast<const float4*>(be)[t];
    float ox = fmaxf(dx * rstd * gv.x + bv.x, 0.f);
    float oy = fmaxf(dy * rstd * gv.y + bv.y, 0.f);
    float oz = fmaxf(dz * rstd * gv.z + bv.z, 0.f);
    float ow = fmaxf(dw * rstd * gv.w + bv.w, 0.f);
    pk.h[0] = __floats2half2_rn(ox, oy);
    pk.h[1] = __floats2half2_rn(oz, ow);
    *reinterpret_cast<uint2*>(xr + 4 * t) = pk.u;
}

// ---------------------------------------------------------------------------
// Fused gate + attention + weighted-context kernel (one block per sample).
// ---------------------------------------------------------------------------
__global__ void __launch_bounds__(128) attn_gate_h(
    const __half* __restrict__ qkv, const __half* __restrict__ gh,
    const float* __restrict__ gw2, const float* __restrict__ gb2,
    __half* __restrict__ wctx, float* __restrict__ gate_out)
{
    __shared__ float sred[12];
    const int b = blockIdx.x, t = threadIdx.x;
    const int lane = t & 31, warp = t >> 5;

    // --- gate softmax over 3 modality logits (single barrier pair) ---
    union { uint2 u; __half2 h[2]; } hv;
    hv.u = *reinterpret_cast<const uint2*>(gh + (size_t)b * 512 + 4 * t);
    float2 h0 = __half22float2(hv.h[0]), h1 = __half22float2(hv.h[1]);
    float p[3];
#pragma unroll
    for (int s = 0; s < 3; s++) {
        float4 w = reinterpret_cast<const float4*>(gw2 + s * 512)[t];
        p[s] = h0.x * w.x + h0.y * w.y + h1.x * w.z + h1.y * w.w;
    }
    float l[3];
    blockSum3_128(p[0], p[1], p[2], sred, l);
    l[0] += gb2[0]; l[1] += gb2[1]; l[2] += gb2[2];
    float m = fmaxf(l[0], fmaxf(l[1], l[2]));
    float e0 = expf(l[0] - m), e1 = expf(l[1] - m), e2 = expf(l[2] - m);
    float inv = 1.f / (e0 + e1 + e2);
    const float g0 = e0 * inv, g1 = e1 * inv, g2 = e2 * inv;
    if (t == 0) {
        gate_out[b * 3 + 0] = g0;
        gate_out[b * 3 + 1] = g1;
        gate_out[b * 3 + 2] = g2;
    }

    // --- attention: warp w handles heads 2w, 2w+1 ---
#pragma unroll
    for (int hh = 0; hh < 2; hh++) {
        const int h = warp * 2 + hh;
        const __half* base = qkv + (size_t)b * 4608 + h * 64 + 2 * lane;
        float2 q[3], k[3], v[3];
#pragma unroll
        for (int i = 0; i < 3; i++) {
            q[i] = __half22float2(*reinterpret_cast<const __half2*>(base + i * 1536));
            k[i] = __half22float2(*reinterpret_cast<const __half2*>(base + i * 1536 + 512));
            v[i] = __half22float2(*reinterpret_cast<const __half2*>(base + i * 1536 + 1024));
        }
        float a[3][3];
#pragma unroll
        for (int i = 0; i < 3; i++)
#pragma unroll
            for (int j = 0; j < 3; j++) {
                float pp = q[i].x * k[j].x + q[i].y * k[j].y;
                a[i][j] = warpSum(pp) * 0.125f;      // 1/sqrt(64)
            }
        float wx = 0.f, wy = 0.f;
#pragma unroll
        for (int i = 0; i < 3; i++) {
            float mm = fmaxf(a[i][0], fmaxf(a[i][1], a[i][2]));
            float x0 = expf(a[i][0] - mm), x1 = expf(a[i][1] - mm), x2 = expf(a[i][2] - mm);
            float iv = 1.f / (x0 + x1 + x2);
            float ox = (x0 * v[0].x + x1 * v[1].x + x2 * v[2].x) * iv;
            float oy = (x0 * v[0].y + x1 * v[1].y + x2 * v[2].y) * iv;
            const float gi = (i == 0) ? g0 : (i == 1) ? g1 : g2;
            wx += gi * ox; wy += gi * oy;
        }
        *reinterpret_cast<__half2*>(wctx + (size_t)b * 512 + h * 64 + 2 * lane)
            = __floats2half2_rn(wx, wy);
    }
}

// classifier head: LN(256) + ReLU + 6-way linear; one warp per sample
__global__ void __launch_bounds__(128) cls_head(
    const float* __restrict__ chid, const float* __restrict__ cg,
    const float* __restrict__ cbeta, const float* __restrict__ cw2,
    const float* __restrict__ cb2, float* __restrict__ logits)
{
    int b = blockIdx.x * 4 + (threadIdx.x >> 5);
    int lane = threadIdx.x & 31;
    const float* hr = chid + (size_t)b * 256;
    float4 h0 = reinterpret_cast<const float4*>(hr)[lane];
    float4 h1 = reinterpret_cast<const float4*>(hr)[lane + 32];
    float sum = warpSum(h0.x + h0.y + h0.z + h0.w + h1.x + h1.y + h1.z + h1.w);
    float mean = sum * (1.f / 256.f);
    h0.x -= mean; h0.y -= mean; h0.z -= mean; h0.w -= mean;
    h1.x -= mean; h1.y -= mean; h1.z -= mean; h1.w -= mean;
    float ss = warpSum(h0.x * h0.x + h0.y * h0.y + h0.z * h0.z + h0.w * h0.w
                     + h1.x * h1.x + h1.y * h1.y + h1.z * h1.z + h1.w * h1.w);
    float rstd = rsqrtf(ss * (1.f / 256.f) + 1e-5f);
    float4 cg0 = reinterpret_cast<const float4*>(cg)[lane];
    float4 cg1 = reinterpret_cast<const float4*>(cg)[lane + 32];
    float4 cb0 = reinterpret_cast<const float4*>(cbeta)[lane];
    float4 cb1 = reinterpret_cast<const float4*>(cbeta)[lane + 32];
    h0.x = fmaxf(h0.x * rstd * cg0.x + cb0.x, 0.f);
    h0.y = fmaxf(h0.y * rstd * cg0.y + cb0.y, 0.f);
    h0.z = fmaxf(h0.z * rstd * cg0.z + cb0.z, 0.f);
    h0.w = fmaxf(h0.w * rstd * cg0.w + cb0.w, 0.f);
    h1.x = fmaxf(h1.x * rstd * cg1.x + cb1.x, 0.f);
    h1.y = fmaxf(h1.y * rstd * cg1.y + cb1.y, 0.f);
    h1.z = fmaxf(h1.z * rstd * cg1.z + cb1.z, 0.f);
    h1.w = fmaxf(h1.w * rstd * cg1.w + cb1.w, 0.f);
#pragma unroll
    for (int c = 0; c < 6; c++) {
        const float4* wr = reinterpret_cast<const float4*>(cw2 + c * 256);
        float4 w0 = wr[lane], w1 = wr[lane + 32];
        float p = h0.x * w0.x + h0.y * w0.y + h0.z * w0.z + h0.w * w0.w
                + h1.x * w1.x + h1.y * w1.y + h1.z * w1.z + h1.w * w1.w;
        p = warpSum(p);
        if (lane == 0) logits[(size_t)b * 6 + c] = p + cb2[c];
    }
}

// ---------------------------------------------------------------------------
extern "C" void kernel_launch(void* const* d_in, const int* in_sizes, int n_in,
                              void* d_out, int out_size)
{
    const float* rgb       = (const float*)d_in[0];
    const float* pose      = (const float*)d_in[1];
    const float* flow      = (const float*)d_in[2];
    const float* rgb_w     = (const float*)d_in[3];
    const float* rgb_b     = (const float*)d_in[4];
    const float* rgb_g     = (const float*)d_in[5];
    const float* rgb_beta  = (const float*)d_in[6];
    const float* pose_w    = (const float*)d_in[7];
    const float* pose_b    = (const float*)d_in[8];
    const float* pose_g    = (const float*)d_in[9];
    const float* pose_beta = (const float*)d_in[10];
    const float* flow_w    = (const float*)d_in[11];
    const float* flow_b    = (const float*)d_in[12];
    const float* flow_g    = (const float*)d_in[13];
    const float* flow_beta = (const float*)d_in[14];
    const float* in_w      = (const float*)d_in[15];
    const float* in_b      = (const float*)d_in[16];
    const float* out_w     = (const float*)d_in[17];
    const float* out_b     = (const float*)d_in[18];
    const float* gw1       = (const float*)d_in[19];
    const float* gb1       = (const float*)d_in[20];
    const float* gw2       = (const float*)d_in[21];
    const float* gb2       = (const float*)d_in[22];
    const float* cw1       = (const float*)d_in[23];
    const float* cb1       = (const float*)d_in[24];
    const float* cg        = (const float*)d_in[25];
    const float* cbeta     = (const float*)d_in[26];
    const float* cw2       = (const float*)d_in[27];
    const float* cb2       = (const float*)d_in[28];

    float* out = (float*)d_out;                 // [B*6 logits | B*3 gate]
    float* logits_out = out;
    float* gate_out   = out + (size_t)BATCH * 6;

    __half *rgb_h, *pose_h, *flow_h, *proj_h, *qkv_h, *wctx_h, *gh_h, *fused_h;
    __half *rgbw_h, *posew_h, *floww_h, *inw_h, *outw_h, *gw1_h, *cw1_h;
    float *chid;
    cudaGetSymbolAddress((void**)&rgb_h,   g_rgb_h);
    cudaGetSymbolAddress((void**)&pose_h,  g_pose_h);
    cudaGetSymbolAddress((void**)&flow_h,  g_flow_h);
    cudaGetSymbolAddress((void**)&proj_h,  g_proj_h);
    cudaGetSymbolAddress((void**)&qkv_h,   g_qkv_h);
    cudaGetSymbolAddress((void**)&wctx_h,  g_wctx_h);
    cudaGetSymbolAddress((void**)&gh_h,    g_gh_h);
    cudaGetSymbolAddress((void**)&fused_h, g_fused_h);
    cudaGetSymbolAddress((void**)&rgbw_h,  g_rgbw_h);
    cudaGetSymbolAddress((void**)&posew_h, g_posew_h);
    cudaGetSymbolAddress((void**)&floww_h, g_floww_h);
    cudaGetSymbolAddress((void**)&inw_h,   g_inw_h);
    cudaGetSymbolAddress((void**)&outw_h,  g_outw_h);
    cudaGetSymbolAddress((void**)&gw1_h,   g_gw1_h);
    cudaGetSymbolAddress((void**)&cw1_h,   g_cw1_h);
    cudaGetSymbolAddress((void**)&chid, g_chid);

    cudaFuncSetAttribute((const void*)gemm_h<0, __half>,
        cudaFuncAttributeMaxDynamicSharedMemorySize, H_SMEM);
    cudaFuncSetAttribute((const void*)gemm_h<0, float>,
        cudaFuncAttributeMaxDynamicSharedMemorySize, H_SMEM);
    cudaFuncSetAttribute((const void*)gemm_batch,
        cudaFuncAttributeMaxDynamicSharedMemorySize, H_SMEM);

    // 0) one fused fp32 -> fp16 convert (inputs + GEMM weights)
    {
        CvtArgs ca;
        ca.src[0] = rgb;    ca.dst[0] = rgb_h;
        ca.src[1] = pose;   ca.dst[1] = pose_h;
        ca.src[2] = flow;   ca.dst[2] = flow_h;
        ca.src[3] = rgb_w;  ca.dst[3] = rgbw_h;
        ca.src[4] = pose_w; ca.dst[4] = posew_h;
        ca.src[5] = flow_w; ca.dst[5] = floww_h;
        ca.src[6] = in_w;   ca.dst[6] = inw_h;
        ca.src[7] = out_w;  ca.dst[7] = outw_h;
        ca.src[8] = gw1;    ca.dst[8] = gw1_h;
        ca.src[9] = cw1;    ca.dst[9] = cw1_h;
        f2h_all<<<(unsigned)((CVT_TOTAL8 + 255) / 256), 256>>>(ca);
    }

    // 1) per-modality projections, ONE launch (longest K first for tail)
    {
        BatchDesc d;
        d.nops = 3;
        // flow (K=1024)
        d.A[0] = flow_h;  d.W[0] = floww_h; d.bias[0] = flow_b;
        d.C[0] = proj_h + 1024; d.K[0] = 1024; d.ldc[0] = 1536;
        d.relu[0] = 0; d.gx[0] = 4; d.cnt[0] = 512;
        // rgb (K=768)
        d.A[1] = rgb_h;   d.W[1] = rgbw_h;  d.bias[1] = rgb_b;
        d.C[1] = proj_h + 0;    d.K[1] = 768;  d.ldc[1] = 1536;
        d.relu[1] = 0; d.gx[1] = 4; d.cnt[1] = 512;
        // pose (K=640)
        d.A[2] = pose_h;  d.W[2] = posew_h; d.bias[2] = pose_b;
        d.C[2] = proj_h + 512;  d.K[2] = 640;  d.ldc[2] = 1536;
        d.relu[2] = 0; d.gx[2] = 4; d.cnt[2] = 512;
        gemm_batch<<<1536, 256, H_SMEM>>>(d);
    }
    // 2) LN + ReLU per (b, modality) row (in-place fp16)
    ln_relu3_h<<<BATCH * 3, 128>>>(proj_h, rgb_g, rgb_beta, pose_g, pose_beta,
                                   flow_g, flow_beta);
    // 3) gate MLP layer 1 + packed QKV projection, ONE launch
    {
        BatchDesc d;
        d.nops = 2;
        // gate1: (16384 x 1536) x (512 x 1536)^T -> gh (ReLU)
        d.A[0] = proj_h; d.W[0] = gw1_h; d.bias[0] = gb1;
        d.C[0] = gh_h;   d.K[0] = 1536;  d.ldc[0] = 512;
        d.relu[0] = 1; d.gx[0] = 4; d.cnt[0] = 512;
        // qkv: (49152 x 512) x (1536 x 512)^T -> qkv_h
        d.A[1] = proj_h; d.W[1] = inw_h; d.bias[1] = in_b;
        d.C[1] = qkv_h;  d.K[1] = 512;   d.ldc[1] = 1536;
        d.relu[1] = 0; d.gx[1] = 12; d.cnt[1] = 4608;
        gemm_batch<<<5120, 256, H_SMEM>>>(d);
    }
    // 4) fused gate softmax + attention + weighted context -> wctx, gate_out
    attn_gate_h<<<BATCH, 128>>>(qkv_h, gh_h, gw2, gb2, wctx_h, gate_out);
    // 5) out-projection on WEIGHTED context (3x fewer FLOPs than per-token)
    gemm_h<0, __half><<<dim3(4, 128), 256, H_SMEM>>>(wctx_h, outw_h, out_b, fused_h, 512, 512);
    // 6) classifier layer 1 -> fp32 chid
    gemm_h<0, float><<<dim3(2, 128), 256, H_SMEM>>>(fused_h, cw1_h, cb1, chid, 512, 256);
    // 7) LN + ReLU + 6-way head
    cls_head<<<BATCH / 4, 128>>>(chid, cg, cbeta, cw2, cb2, logits_out);
}